// round 14
// baseline (speedup 1.0000x reference)
#include <cuda_runtime.h>
#include <cuda_fp16.h>
#include <math.h>

// ---------------- problem constants ----------------
constexpr int kT   = 1024;
constexpr int kD   = 1024;
constexpr int kH   = 16;
constexpr int kDH  = 64;
constexpr int kE   = 8;
constexpr int kDFF = 4096;
constexpr int kSlots = 3072;   // 2048 assignments + per-expert pad to 128
constexpr int kProjKS = 4;     // proj split-K factor

// ---------------- device scratch ----------------
__device__ float g_x[kT * kD];
__device__ float g_q[kH * kT * kDH];
__device__ float g_kT[kH * kDH * kT];   // K transposed: [h][dh][t]
__device__ float g_v[kH * kT * kDH];
__device__ float g_attn[kT * kD];
__device__ float g_pp[kProjKS * kT * kD];   // proj split-K partials
__device__ float g_emb2[kT * kD];
__device__ float g_y[kT * kD];
__device__ __half g_h[kSlots * kDFF];   // expert hidden, fp16
__device__ float g_yo[kSlots * kD];
__device__ int   g_ids[kT * 2];
__device__ float g_gates[kT * 2];
__device__ int   g_counts[kE];
__device__ int   g_poff[kE + 1];
__device__ int   g_cursor[kE];
__device__ int   g_slot_token[kSlots];
__device__ int   g_slotpos[kT * 2];
__device__ float g_impsum[kE];

// ---------------- mma helpers ----------------
__device__ __forceinline__ unsigned f2tf32(float x) {
    unsigned y; asm("cvt.rna.tf32.f32 %0, %1;" : "=r"(y) : "f"(x)); return y;
}
__device__ __forceinline__ void mma_tf32(float c[4], const unsigned a[4], const unsigned b[2]) {
    asm volatile("mma.sync.aligned.m16n8k8.row.col.f32.tf32.tf32.f32 "
        "{%0,%1,%2,%3}, {%4,%5,%6,%7}, {%8,%9}, {%0,%1,%2,%3};\n"
        : "+f"(c[0]), "+f"(c[1]), "+f"(c[2]), "+f"(c[3])
        : "r"(a[0]), "r"(a[1]), "r"(a[2]), "r"(a[3]), "r"(b[0]), "r"(b[1]));
}
__device__ __forceinline__ void mma_f16(float c[4], const unsigned a[4], const unsigned b[2]) {
    asm volatile("mma.sync.aligned.m16n8k16.row.col.f32.f16.f16.f32 "
        "{%0,%1,%2,%3}, {%4,%5,%6,%7}, {%8,%9}, {%0,%1,%2,%3};\n"
        : "+f"(c[0]), "+f"(c[1]), "+f"(c[2]), "+f"(c[3])
        : "r"(a[0]), "r"(a[1]), "r"(a[2]), "r"(a[3]), "r"(b[0]), "r"(b[1]));
}
__device__ __forceinline__ unsigned pk2(float a, float b) {
    __half2 h = __floats2half2_rn(a, b);
    return *(unsigned*)&h;
}

constexpr int ASTR = 20;
constexpr int BSTR = 136;

// ======== M128 tile (256 thr, warp tile 32x64, double-buffered) ========
#define GEMM16_SMEM \
    __shared__ __align__(16) unsigned As[2][128 * ASTR]; \
    __shared__ __align__(16) unsigned Bs[2][16 * BSTR];

#define GEMM16_COMPUTE(buf) \
    _Pragma("unroll") \
    for (int p0 = 0; p0 < 16; p0 += 8) { \
        unsigned bf[8][2]; \
        _Pragma("unroll") \
        for (int nt = 0; nt < 8; nt++) { \
            int n = wn * 64 + nt * 8 + (lane >> 2); \
            bf[nt][0] = Bs[buf][(p0 + (lane & 3)) * BSTR + n]; \
            bf[nt][1] = Bs[buf][(p0 + 4 + (lane & 3)) * BSTR + n]; \
        } \
        _Pragma("unroll") \
        for (int mt = 0; mt < 2; mt++) { \
            int m = wm * 32 + mt * 16 + (lane >> 2); \
            unsigned af[4]; \
            af[0] = As[buf][m * ASTR + p0 + (lane & 3)]; \
            af[1] = As[buf][(m + 8) * ASTR + p0 + (lane & 3)]; \
            af[2] = As[buf][m * ASTR + p0 + 4 + (lane & 3)]; \
            af[3] = As[buf][(m + 8) * ASTR + p0 + 4 + (lane & 3)]; \
            _Pragma("unroll") \
            for (int nt = 0; nt < 8; nt++) mma_f16(acc[mt][nt], af, bf[nt]); \
        } \
    }

#define GEMM16_STORE_REGS(buf) \
    _Pragma("unroll") \
    for (int p = 0; p < 4; p++) \
        *(uint2*)&As[buf][((tid >> 3) + p * 32) * ASTR + (tid & 7) * 2] = pa[p]; \
    _Pragma("unroll") \
    for (int p = 0; p < 2; p++) \
        *(uint4*)&Bs[buf][((tid >> 5) + p * 8) * BSTR + (tid & 31) * 4] = pb[p];

// ---------------- misc helpers ----------------
__device__ __forceinline__ float block_reduce_sum(float v) {
    __shared__ float sh[32];
    int lane = threadIdx.x & 31, w = threadIdx.x >> 5;
    #pragma unroll
    for (int o = 16; o > 0; o >>= 1) v += __shfl_xor_sync(0xffffffffu, v, o);
    if (lane == 0) sh[w] = v;
    __syncthreads();
    if (w == 0) {
        v = (lane < (int)(blockDim.x >> 5)) ? sh[lane] : 0.f;
        #pragma unroll
        for (int o = 16; o > 0; o >>= 1) v += __shfl_xor_sync(0xffffffffu, v, o);
        if (lane == 0) sh[0] = v;
    }
    __syncthreads();
    float r = sh[0];
    __syncthreads();
    return r;
}

// ---------------- LN1 (+ folded scratch reset) ----------------
__global__ void ln_kernel(const float* __restrict__ in, const float* __restrict__ g,
                          const float* __restrict__ b, float* __restrict__ out) {
    int gi = blockIdx.x * blockDim.x + threadIdx.x;
    if (gi < kSlots) g_slot_token[gi] = -1;
    if (gi < kE) { g_counts[gi] = 0; g_impsum[gi] = 0.f; }

    int row = blockIdx.x;
    const float* x = in + (size_t)row * kD;
    float s = 0.f;
    for (int i = threadIdx.x; i < kD; i += blockDim.x) s += x[i];
    float mean = block_reduce_sum(s) * (1.f / kD);
    float v = 0.f;
    for (int i = threadIdx.x; i < kD; i += blockDim.x) {
        float d = x[i] - mean; v += d * d;
    }
    float var = block_reduce_sum(v) * (1.f / kD);
    float rstd = rsqrtf(var + 1e-6f);
    float* o = out + (size_t)row * kD;
    for (int i = threadIdx.x; i < kD; i += blockDim.x)
        o[i] = (x[i] - mean) * rstd * g[i] + b[i];
}

// ---------------- fused proj-reduce + residual + LN2 + router ----------------
// emb2 = emb + sum_z pp[z] + bproj ; y = LN(emb2) ; router(y)
__global__ void ln2_router_kernel(const float* __restrict__ emb,
                                  const float* __restrict__ bproj,
                                  const float* __restrict__ g, const float* __restrict__ b,
                                  float* __restrict__ yout,
                                  const float* __restrict__ Wr, const float* __restrict__ br) {
    int row = blockIdx.x;
    int c4 = threadIdx.x * 4;   // 256 threads x 4 cols = 1024
    size_t base = (size_t)row * kD + c4;

    float4 e2 = *(const float4*)&emb[base];
    float4 bb = *(const float4*)&bproj[c4];
    e2.x += bb.x; e2.y += bb.y; e2.z += bb.z; e2.w += bb.w;
    #pragma unroll
    for (int z = 0; z < kProjKS; z++) {
        float4 p = *(const float4*)&g_pp[(size_t)z * kT * kD + base];
        e2.x += p.x; e2.y += p.y; e2.z += p.z; e2.w += p.w;
    }
    *(float4*)&g_emb2[base] = e2;

    float s = e2.x + e2.y + e2.z + e2.w;
    float mean = block_reduce_sum(s) * (1.f / kD);
    float d0 = e2.x - mean, d1 = e2.y - mean, d2 = e2.z - mean, d3 = e2.w - mean;
    float var = block_reduce_sum(d0 * d0 + d1 * d1 + d2 * d2 + d3 * d3) * (1.f / kD);
    float rstd = rsqrtf(var + 1e-6f);

    float4 gg = *(const float4*)&g[c4];
    float4 bt = *(const float4*)&b[c4];
    float val[4];
    val[0] = d0 * rstd * gg.x + bt.x;
    val[1] = d1 * rstd * gg.y + bt.y;
    val[2] = d2 * rstd * gg.z + bt.z;
    val[3] = d3 * rstd * gg.w + bt.w;
    *(float4*)&yout[base] = *(float4*)val;

    float rs[kE];
    #pragma unroll
    for (int e = 0; e < kE; e++) rs[e] = 0.f;
    #pragma unroll
    for (int j = 0; j < 4; j++) {
        const float* wr = Wr + (size_t)(c4 + j) * kE;
        #pragma unroll
        for (int e = 0; e < kE; e++) rs[e] += val[j] * wr[e];
    }
    #pragma unroll
    for (int e = 0; e < kE; e++) rs[e] = block_reduce_sum(rs[e]);
    if (threadIdx.x == 0) {
        float w[kE];
        float mx = -1e30f;
        #pragma unroll
        for (int e = 0; e < kE; e++) { w[e] = rs[e] + br[e]; mx = fmaxf(mx, w[e]); }
        float sum = 0.f;
        #pragma unroll
        for (int e = 0; e < kE; e++) { w[e] = __expf(w[e] - mx); sum += w[e]; }
        float inv = 1.f / sum;
        #pragma unroll
        for (int e = 0; e < kE; e++) w[e] *= inv;
        int i0 = 0;
        #pragma unroll
        for (int e = 1; e < kE; e++) if (w[e] > w[i0]) i0 = e;
        int i1 = -1;
        #pragma unroll
        for (int e = 0; e < kE; e++) if (e != i0 && (i1 < 0 || w[e] > w[i1])) i1 = e;
        float norm = w[i0] + w[i1];
        g_ids[row * 2]     = i0;
        g_ids[row * 2 + 1] = i1;
        g_gates[row * 2]     = w[i0] / norm;
        g_gates[row * 2 + 1] = w[i1] / norm;
        atomicAdd(&g_counts[i0], 1);
        atomicAdd(&g_counts[i1], 1);
        #pragma unroll
        for (int e = 0; e < kE; e++) atomicAdd(&g_impsum[e], w[e]);
    }
}

// ---------------- QKV fp16 GEMM + fused RoPE (K written transposed), M128 ----------------
__global__ __launch_bounds__(256) void qkv_kernel(
    const float* __restrict__ x,
    const float* __restrict__ WQ, const float* __restrict__ WK, const float* __restrict__ WV,
    float* __restrict__ Qo, float* __restrict__ KTo, float* __restrict__ Vo) {
    GEMM16_SMEM
    int tid = threadIdx.x, lane = tid & 31, w = tid >> 5;
    int wm = w & 3, wn = w >> 2;
    int r0 = blockIdx.x * 128;
    int n0 = blockIdx.y * 128;
    int z = blockIdx.z;
    const float* W = (z == 0) ? WQ : (z == 1) ? WK : WV;

    int bn4 = (tid & 31) * 4;
    int bh = (n0 + bn4) >> 6, be = (n0 + bn4) & 63;
    uint2 pa[4];
    uint4 pb[2];

    #define QKV_LOAD_REGS(k0_) { \
        _Pragma("unroll") \
        for (int p = 0; p < 4; p++) { \
            int m = (tid >> 3) + p * 32; \
            float4 v = *(const float4*)&x[(size_t)(r0 + m) * kD + (k0_) + (tid & 7) * 4]; \
            pa[p].x = pk2(v.x, v.y); pa[p].y = pk2(v.z, v.w); \
        } \
        _Pragma("unroll") \
        for (int p = 0; p < 2; p++) { \
            int kp = (tid >> 5) + p * 8; \
            const float* b0p = &W[((size_t)bh * kD + (k0_) + 2 * kp) * kDH + be]; \
            float4 r0v = *(const float4*)b0p; \
            float4 r1v = *(const float4*)(b0p + kDH); \
            pb[p].x = pk2(r0v.x, r1v.x); pb[p].y = pk2(r0v.y, r1v.y); \
            pb[p].z = pk2(r0v.z, r1v.z); pb[p].w = pk2(r0v.w, r1v.w); \
        } \
    }

    float acc[2][8][4] = {};
    QKV_LOAD_REGS(0)
    GEMM16_STORE_REGS(0)
    __syncthreads();
    for (int k0 = 0, i = 0; k0 < kD; k0 += 32, i++) {
        if (k0 + 32 < kD) QKV_LOAD_REGS(k0 + 32)
        GEMM16_COMPUTE(i & 1)
        if (k0 + 32 < kD) GEMM16_STORE_REGS((i + 1) & 1)
        __syncthreads();
    }
    #undef QKV_LOAD_REGS

    #pragma unroll
    for (int mt = 0; mt < 2; mt++) {
        #pragma unroll
        for (int nt = 0; nt < 8; nt++) {
            int n = n0 + wn * 64 + nt * 8 + (lane & 3) * 2;
            int h = n >> 6, e = n & 63;
            #pragma unroll
            for (int half = 0; half < 2; half++) {
                int t = r0 + wm * 32 + mt * 16 + (lane >> 2) + half * 8;
                float v0 = acc[mt][nt][half * 2 + 0];
                float v1 = acc[mt][nt][half * 2 + 1];
                if (z < 2) {
                    int p = e >> 1;
                    float theta = exp2f(-(float)p * (13.287712379549449f / 32.f));
                    float sn, cs;
                    sincosf((float)t * theta, &sn, &cs);
                    float w0 = v0 * cs - v1 * sn;
                    float w1 = v1 * cs + v0 * sn;
                    v0 = w0; v1 = w1;
                }
                if (z == 1) {
                    KTo[((size_t)h * kDH + e) * kT + t]     = v0;
                    KTo[((size_t)h * kDH + e + 1) * kT + t] = v1;
                } else {
                    float* O = (z == 0) ? Qo : Vo;
                    float2 r2 = { v0, v1 };
                    *(float2*)&O[((size_t)h * kT + t) * kDH + e] = r2;
                }
            }
        }
    }
}

// ---------------- flash attention (tf32 mma) ----------------
constexpr int KSTR = 72;
constexpr int PSTR = 68;
constexpr int ATTN_SMEM_BYTES = (64 * PSTR + 2 * 64 * KSTR) * 4;   // 54272

__global__ __launch_bounds__(128) void attn_kernel(
    const float* __restrict__ Q, const float* __restrict__ KTr,
    const float* __restrict__ V, float* __restrict__ A) {
    extern __shared__ __align__(16) unsigned sm_attn[];
    unsigned* QPs = sm_attn;
    unsigned* Ks  = sm_attn + 64 * PSTR;
    unsigned* Vs  = Ks + 64 * KSTR;
    int tid = threadIdx.x, lane = tid & 31, w = tid >> 5;
    int h = blockIdx.y;
    int qt = (int)gridDim.x - 1 - (int)blockIdx.x;
    int q0 = qt * 64;
    const float* Qh  = Q   + ((size_t)h * kT + q0) * kDH;
    const float* KTh = KTr + (size_t)h * kDH * kT;
    const float* Vh  = V   + (size_t)h * kT * kDH;

    #pragma unroll
    for (int it = 0; it < 8; it++) {
        int idx = tid + it * 128;
        int m = idx >> 4, dh4 = (idx & 15) * 4;
        float4 v = *(const float4*)&Qh[(size_t)m * kDH + dh4];
        uint4 u = { f2tf32(v.x), f2tf32(v.y), f2tf32(v.z), f2tf32(v.w) };
        *(uint4*)&QPs[m * PSTR + dh4] = u;
    }
    __syncthreads();
    unsigned qf[8][4];
    {
        int m = w * 16 + (lane >> 2);
        #pragma unroll
        for (int kk = 0; kk < 8; kk++) {
            qf[kk][0] = QPs[m * PSTR + kk * 8 + (lane & 3)];
            qf[kk][1] = QPs[(m + 8) * PSTR + kk * 8 + (lane & 3)];
            qf[kk][2] = QPs[m * PSTR + kk * 8 + 4 + (lane & 3)];
            qf[kk][3] = QPs[(m + 8) * PSTR + kk * 8 + 4 + (lane & 3)];
        }
    }

    float acc_o[8][4] = {};
    float m0 = -1e30f, m1 = -1e30f, l0 = 0.f, l1 = 0.f;

    for (int kt = 0; kt <= qt; kt++) {
        int k0 = kt * 64;
        __syncthreads();
        #pragma unroll
        for (int it = 0; it < 8; it++) {
            int idx = tid + it * 128;
            int dh = idx >> 4, key4 = (idx & 15) * 4;
            float4 v = *(const float4*)&KTh[(size_t)dh * kT + k0 + key4];
            uint4 u = { f2tf32(v.x), f2tf32(v.y), f2tf32(v.z), f2tf32(v.w) };
            *(uint4*)&Ks[dh * KSTR + key4] = u;
        }
        #pragma unroll
        for (int it = 0; it < 8; it++) {
            int idx = tid + it * 128;
            int key = idx >> 4, dh4 = (idx & 15) * 4;
            float4 v = *(const float4*)&Vh[(size_t)(k0 + key) * kDH + dh4];
            uint4 u = { f2tf32(v.x), f2tf32(v.y), f2tf32(v.z), f2tf32(v.w) };
            *(uint4*)&Vs[key * KSTR + dh4] = u;
        }
        __syncthreads();

        float s_acc[8][4] = {};
        #pragma unroll
        for (int kk = 0; kk < 8; kk++) {
            #pragma unroll
            for (int nt = 0; nt < 8; nt++) {
                unsigned bf[2];
                bf[0] = Ks[(kk * 8 + (lane & 3)) * KSTR + nt * 8 + (lane >> 2)];
                bf[1] = Ks[(kk * 8 + 4 + (lane & 3)) * KSTR + nt * 8 + (lane >> 2)];
                mma_tf32(s_acc[nt], qf[kk], bf);
            }
        }

        float rm0 = -1e30f, rm1 = -1e30f;
        int gq0 = q0 + w * 16 + (lane >> 2);
        #pragma unroll
        for (int nt = 0; nt < 8; nt++) {
            #pragma unroll
            for (int c = 0; c < 4; c++) {
                float v = s_acc[nt][c] * 0.125f;
                if (kt == qt) {
                    int key = k0 + nt * 8 + 2 * (lane & 3) + (c & 1);
                    int gq = gq0 + (c >> 1) * 8;
                    if (key > gq) v = -1e30f;
                }
                s_acc[nt][c] = v;
                if ((c >> 1) == 0) rm0 = fmaxf(rm0, v); else rm1 = fmaxf(rm1, v);
            }
        }
        #pragma unroll
        for (int o = 1; o <= 2; o <<= 1) {
            rm0 = fmaxf(rm0, __shfl_xor_sync(0xffffffffu, rm0, o));
            rm1 = fmaxf(rm1, __shfl_xor_sync(0xffffffffu, rm1, o));
        }
        float nm0 = fmaxf(m0, rm0), nm1 = fmaxf(m1, rm1);
        float sc0 = __expf(m0 - nm0), sc1 = __expf(m1 - nm1);
        m0 = nm0; m1 = nm1;

        float rs0 = 0.f, rs1 = 0.f;
        int prow = w * 16 + (lane >> 2);
        #pragma unroll
        for (int nt = 0; nt < 8; nt++) {
            float p0 = __expf(s_acc[nt][0] - nm0);
            float p1 = __expf(s_acc[nt][1] - nm0);
            float p2 = __expf(s_acc[nt][2] - nm1);
            float p3 = __expf(s_acc[nt][3] - nm1);
            rs0 += p0 + p1; rs1 += p2 + p3;
            uint2 u01 = { f2tf32(p0), f2tf32(p1) };
            uint2 u23 = { f2tf32(p2), f2tf32(p3) };
            *(uint2*)&QPs[prow * PSTR + nt * 8 + 2 * (lane & 3)] = u01;
            *(uint2*)&QPs[(prow + 8) * PSTR + nt * 8 + 2 * (lane & 3)] = u23;
        }
        #pragma unroll
        for (int o = 1; o <= 2; o <<= 1) {
            rs0 += __shfl_xor_sync(0xffffffffu, rs0, o);
            rs1 += __shfl_xor_sync(0xffffffffu, rs1, o);
        }
        l0 = l0 * sc0 + rs0;
        l1 = l1 * sc1 + rs1;
        #pragma unroll
        for (int nt = 0; nt < 8; nt++) {
            acc_o[nt][0] *= sc0; acc_o[nt][1] *= sc0;
            acc_o[nt][2] *= sc1; acc_o[nt][3] *= sc1;
        }
        __syncwarp();

        #pragma unroll
        for (int kk = 0; kk < 8; kk++) {
            unsigned pf[4];
            int m = w * 16 + (lane >> 2);
            pf[0] = QPs[m * PSTR + kk * 8 + (lane & 3)];
            pf[1] = QPs[(m + 8) * PSTR + kk * 8 + (lane & 3)];
            pf[2] = QPs[m * PSTR + kk * 8 + 4 + (lane & 3)];
            pf[3] = QPs[(m + 8) * PSTR + kk * 8 + 4 + (lane & 3)];
            #pragma unroll
            for (int nt = 0; nt < 8; nt++) {
                unsigned bf[2];
                bf[0] = Vs[(kk * 8 + (lane & 3)) * KSTR + nt * 8 + (lane >> 2)];
                bf[1] = Vs[(kk * 8 + 4 + (lane & 3)) * KSTR + nt * 8 + (lane >> 2)];
                mma_tf32(acc_o[nt], pf, bf);
            }
        }
    }

    float inv0 = 1.f / l0, inv1 = 1.f / l1;
    int gq0 = q0 + w * 16 + (lane >> 2);
    #pragma unroll
    for (int nt = 0; nt < 8; nt++) {
        int col = h * kDH + nt * 8 + 2 * (lane & 3);
        float2 r0 = { acc_o[nt][0] * inv0, acc_o[nt][1] * inv0 };
        float2 r1 = { acc_o[nt][2] * inv1, acc_o[nt][3] * inv1 };
        *(float2*)&A[(size_t)gq0 * kD + col] = r0;
        *(float2*)&A[(size_t)(gq0 + 8) * kD + col] = r1;
    }
}

// ---------------- proj fp16 GEMM, M128 tile, split-K=4 -> partials ----------------
__global__ __launch_bounds__(256) void proj_kernel(
    const float* __restrict__ A, const float* __restrict__ W) {
    GEMM16_SMEM
    int tid = threadIdx.x, lane = tid & 31, w = tid >> 5;
    int wm = w & 3, wn = w >> 2;
    int r0 = blockIdx.x * 128;
    int n0 = blockIdx.y * 128;
    int kz = blockIdx.z;                       // split-K slice
    int kbeg = kz * (kD / kProjKS);            // 256-deep slice
    int kend = kbeg + kD / kProjKS;
    float* P = &g_pp[(size_t)kz * kT * kD];

    uint2 pa[4];
    uint4 pb[2];

    #define PROJ_LOAD_REGS(k0_) { \
        _Pragma("unroll") \
        for (int p = 0; p < 4; p++) { \
            int m = (tid >> 3) + p * 32; \
            float4 v = *(const float4*)&A[(size_t)(r0 + m) * kD + (k0_) + (tid & 7) * 4]; \
            pa[p].x = pk2(v.x, v.y); pa[p].y = pk2(v.z, v.w); \
        } \
        _Pragma("unroll") \
        for (int p = 0; p < 2; p++) { \
            int kp = (tid >> 5) + p * 8; \
            const float* b0p = &W[(size_t)((k0_) + 2 * kp) * kD + n0 + (tid & 31) * 4]; \
            float4 r0v = *(const float4*)b0p; \
            float4 r1v = *(const float4*)(b0p + kD); \
            pb[p].x = pk2(r0v.x, r1v.x); pb[p].y = pk2(r0v.y, r1v.y); \
            pb[p].z = pk2(r0v.z, r1v.z); pb[p].w = pk2(r0v.w, r1v.w); \
        } \
    }

    float acc[2][8][4] = {};
    PROJ_LOAD_REGS(kbeg)
    GEMM16_STORE_REGS(0)
    __syncthreads();
    for (int k0 = kbeg, i = 0; k0 < kend; k0 += 32, i++) {
        if (k0 + 32 < kend) PROJ_LOAD_REGS(k0 + 32)
        GEMM16_COMPUTE(i & 1)
        if (k0 + 32 < kend) GEMM16_STORE_REGS((i + 1) & 1)
        __syncthreads();
    }
    #undef PROJ_LOAD_REGS

    #pragma unroll
    for (int mt = 0; mt < 2; mt++) {
        #pragma unroll
        for (int nt = 0; nt < 8; nt++) {
            int c = n0 + wn * 64 + nt * 8 + (lane & 3) * 2;
            #pragma unroll
            for (int half = 0; half < 2; half++) {
                int r = r0 + wm * 32 + mt * 16 + (lane >> 2) + half * 8;
                float2 r2 = { acc[mt][nt][half * 2 + 0], acc[mt][nt][half * 2 + 1] };
                *(float2*)&P[(size_t)r * kD + c] = r2;
            }
        }
    }
}

// ---------------- fused offsets + aux + scatter (single block) ----------------
__global__ void offsets_scatter_kernel(float* __restrict__ out, int out_size) {
    int tid = threadIdx.x;
    if (tid == 0) {
        int off = 0;
        g_poff[0] = 0;
        for (int e = 0; e < kE; e++) {
            int pc = (g_counts[e] + 127) & ~127;
            off += pc;
            g_poff[e + 1] = off;
            g_cursor[e] = g_poff[e];
        }
        float aux = 0.f;
        for (int e = 0; e < kE; e++) {
            float imp = g_impsum[e] / (float)kT;
            float dlt = imp - 1.f / (float)kE;
            aux += dlt * dlt;
        }
        aux *= 1.f / (float)kE;
        if (out_size > kT * kD) out[kT * kD] = aux;
    }
    __syncthreads();
    for (int i = tid; i < kT * 2; i += blockDim.x) {
        int e = g_ids[i];
        int pos = atomicAdd(&g_cursor[e], 1);
        g_slot_token[pos] = i >> 1;
        g_slotpos[i] = pos;
    }
}

// ---------------- F1 fp16 GEMM: h = relu(...) -> fp16 out, M128 ----------------
__global__ __launch_bounds__(256) void f1_kernel(
    const float* __restrict__ y, const float* __restrict__ W1,
    const float* __restrict__ b1) {
    GEMM16_SMEM
    __shared__ int tok[128];
    __shared__ int sh_total, sh_e;
    int tid = threadIdx.x, lane = tid & 31, w = tid >> 5;
    int wm = w & 3, wn = w >> 2;
    int s0 = blockIdx.x * 128;
    if (tid == 0) {
        sh_total = g_poff[kE];
        int e = 0;
        while (e < kE - 1 && s0 >= g_poff[e + 1]) e++;
        sh_e = e;
    }
    if (tid < 128) tok[tid] = g_slot_token[s0 + tid];
    __syncthreads();
    if (s0 >= sh_total) return;
    int e = sh_e;
    const float* W = W1 + (size_t)e * kD * kDFF;
    int f0 = blockIdx.y * 128;
    int atok[4];
    #pragma unroll
    for (int p = 0; p < 4; p++) atok[p] = tok[(tid >> 3) + p * 32];

    uint2 pa[4];
    uint4 pb[2];

    #define F1_LOAD_REGS(k0_) { \
        _Pragma("unroll") \
        for (int p = 0; p < 4; p++) { \
            int t = atok[p]; \
            if (t >= 0) { \
                float4 v = *(const float4*)&y[(size_t)t * kD + (k0_) + (tid & 7) * 4]; \
                pa[p].x = pk2(v.x, v.y); pa[p].y = pk2(v.z, v.w); \
            } else { pa[p].x = 0u; pa[p].y = 0u; } \
        } \
        _Pragma("unroll") \
        for (int p = 0; p < 2; p++) { \
            int kp = (tid >> 5) + p * 8; \
            const float* b0p = &W[(size_t)((k0_) + 2 * kp) * kDFF + f0 + (tid & 31) * 4]; \
            float4 r0v = *(const float4*)b0p; \
            float4 r1v = *(const float4*)(b0p + kDFF); \
            pb[p].x = pk2(r0v.x, r1v.x); pb[p].y = pk2(r0v.y, r1v.y); \
            pb[p].z = pk2(r0v.z, r1v.z); pb[p].w = pk2(r0v.w, r1v.w); \
        } \
    }

    float acc[2][8][4] = {};
    F1_LOAD_REGS(0)
    GEMM16_STORE_REGS(0)
    __syncthreads();
    for (int k0 = 0, i = 0; k0 < kD; k0 += 32, i++) {
        if (k0 + 32 < kD) F1_LOAD_REGS(k0 + 32)
        GEMM16_COMPUTE(i & 1)
        if (k0 + 32 < kD) GEMM16_STORE_REGS((i + 1) & 1)
        __syncthreads();
    }
    #undef F1_LOAD_REGS

    #pragma unroll
    for (int mt = 0; mt < 2; mt++) {
        #pragma unroll
        for (int nt = 0; nt < 8; nt++) {
            int c = f0 + wn * 64 + nt * 8 + (lane & 3) * 2;
            float bb0 = b1[(size_t)e * kDFF + c];
            float bb1 = b1[(size_t)e * kDFF + c + 1];
            #pragma unroll
            for (int half = 0; half < 2; half++) {
                int r = s0 + wm * 32 + mt * 16 + (lane >> 2) + half * 8;
                float h0 = fmaxf(acc[mt][nt][half * 2 + 0] + bb0, 0.f);
                float h1 = fmaxf(acc[mt][nt][half * 2 + 1] + bb1, 0.f);
                __half2 hv = __floats2half2_rn(h0, h1);
                *(__half2*)&g_h[(size_t)r * kDFF + c] = hv;
            }
        }
    }
}

// ---------------- F2 fp16 GEMM: yo = h @ W2[e] + b2[e], M128 ----------------
__global__ __launch_bounds__(256) void f2_kernel(
    const float* __restrict__ W2, const float* __restrict__ b2) {
    GEMM16_SMEM
    __shared__ int sh_total, sh_e;
    int tid = threadIdx.x, lane = tid & 31, w = tid >> 5;
    int wm = w & 3, wn = w >> 2;
    int s0 = blockIdx.x * 128;
    if (tid == 0) {
        sh_total = g_poff[kE];
        int e = 0;
        while (e < kE - 1 && s0 >= g_poff[e + 1]) e++;
        sh_e = e;
    }
    __syncthreads();
    if (s0 >= sh_total) return;
    int e = sh_e;
    const float* W = W2 + (size_t)e * kDFF * kD;
    int c0 = blockIdx.y * 128;

    uint2 pa[4];
    uint4 pb[2];

    #define F2_LOAD_REGS(k0_) { \
        _Pragma("unroll") \
        for (int p = 0; p < 4; p++) { \
            int m = (tid >> 3) + p * 32; \
            pa[p] = *(const uint2*)&g_h[(size_t)(s0 + m) * kDFF + (k0_) + (tid & 7) * 4]; \
        } \
        _Pragma("unroll") \
        for (int p = 0; p < 2; p++) { \
            int kp = (tid >> 5) + p * 8; \
            const float* b0p = &W[(size_t)((k0_) + 2 * kp) * kD + c0 + (tid & 31) * 4]; \
            float4 r0v = *(const float4*)b0p; \
            float4 r1v = *(const float4*)(b0p + kD); \
            pb[p].x = pk2(r0v.x, r1v.x); pb[p].y = pk2(r0v.y, r1v.y); \
            pb[p].z = pk2(r0v.z, r1v.z); pb[p].w = pk2(r0v.w, r1v.w); \
        } \
    }

    float acc[2][8][4] = {};
    F2_LOAD_REGS(0)
    GEMM16_STORE_REGS(0)
    __syncthreads();
    for (int k0 = 0, i = 0; k0 < kDFF; k0 += 32, i++) {
        if (k0 + 32 < kDFF) F2_LOAD_REGS(k0 + 32)
        GEMM16_COMPUTE(i & 1)
        if (k0 + 32 < kDFF) GEMM16_STORE_REGS((i + 1) & 1)
        __syncthreads();
    }
    #undef F2_LOAD_REGS

    #pragma unroll
    for (int mt = 0; mt < 2; mt++) {
        #pragma unroll
        for (int nt = 0; nt < 8; nt++) {
            int c = c0 + wn * 64 + nt * 8 + (lane & 3) * 2;
            float bb0 = b2[(size_t)e * kD + c];
            float bb1 = b2[(size_t)e * kD + c + 1];
            #pragma unroll
            for (int half = 0; half < 2; half++) {
                int r = s0 + wm * 32 + mt * 16 + (lane >> 2) + half * 8;
                float2 r2;
                r2.x = acc[mt][nt][half * 2 + 0] + bb0;
                r2.y = acc[mt][nt][half * 2 + 1] + bb1;
                *(float2*)&g_yo[(size_t)r * kD + c] = r2;
            }
        }
    }
}

// ---------------- combine ----------------
__global__ void combine_kernel(float* __restrict__ out) {
    int idx4 = blockIdx.x * blockDim.x + threadIdx.x;
    if (idx4 >= kT * kD / 4) return;
    int idx = idx4 * 4;
    int n = idx >> 10;
    int d = idx & (kD - 1);
    int p0 = g_slotpos[n * 2], p1 = g_slotpos[n * 2 + 1];
    float g0 = g_gates[n * 2], g1 = g_gates[n * 2 + 1];
    float4 base = *(const float4*)&g_emb2[idx];
    float4 y0 = *(const float4*)&g_yo[(size_t)p0 * kD + d];
    float4 y1 = *(const float4*)&g_yo[(size_t)p1 * kD + d];
    float4 r;
    r.x = base.x + g0 * y0.x + g1 * y1.x;
    r.y = base.y + g0 * y0.y + g1 * y1.y;
    r.z = base.z + g0 * y0.z + g1 * y1.z;
    r.w = base.w + g0 * y0.w + g1 * y1.w;
    *(float4*)&out[idx] = r;
}

// ---------------- launch ----------------
extern "C" void kernel_launch(void* const* d_in, const int* in_sizes, int n_in,
                              void* d_out, int out_size) {
    const float* emb    = (const float*)d_in[0];
    const float* gamma1 = (const float*)d_in[1];
    const float* beta1  = (const float*)d_in[2];
    const float* WQ     = (const float*)d_in[3];
    const float* WK     = (const float*)d_in[4];
    const float* WV     = (const float*)d_in[5];
    const float* Wproj  = (const float*)d_in[6];
    const float* bproj  = (const float*)d_in[7];
    const float* gamma2 = (const float*)d_in[8];
    const float* beta2  = (const float*)d_in[9];
    const float* Wr     = (const float*)d_in[10];
    const float* br     = (const float*)d_in[11];
    const float* W1     = (const float*)d_in[12];
    const float* b1     = (const float*)d_in[13];
    const float* W2     = (const float*)d_in[14];
    const float* b2     = (const float*)d_in[15];
    float* out = (float*)d_out;

    float* gx;    cudaGetSymbolAddress((void**)&gx, g_x);
    float* gq;    cudaGetSymbolAddress((void**)&gq, g_q);
    float* gkT;   cudaGetSymbolAddress((void**)&gkT, g_kT);
    float* gv;    cudaGetSymbolAddress((void**)&gv, g_v);
    float* gattn; cudaGetSymbolAddress((void**)&gattn, g_attn);
    float* gy;    cudaGetSymbolAddress((void**)&gy, g_y);

    cudaFuncSetAttribute(attn_kernel, cudaFuncAttributeMaxDynamicSharedMemorySize,
                         ATTN_SMEM_BYTES);

    ln_kernel<<<kT, 256>>>(emb, gamma1, beta1, gx);
    qkv_kernel<<<dim3(kT / 128, (kH * kDH) / 128, 3), 256>>>(gx, WQ, WK, WV, gq, gkT, gv);
    attn_kernel<<<dim3(kT / 64, kH), 128, ATTN_SMEM_BYTES>>>(gq, gkT, gv, gattn);
    proj_kernel<<<dim3(kT / 128, kD / 128, kProjKS), 256>>>(gattn, Wproj);
    ln2_router_kernel<<<kT, 256>>>(emb, bproj, gamma2, beta2, gy, Wr, br);
    offsets_scatter_kernel<<<1, 1024>>>(out, out_size);
    f1_kernel<<<dim3(kSlots / 128, kDFF / 128), 256>>>(gy, W1, b1);
    f2_kernel<<<dim3(kSlots / 128, kD / 128), 256>>>(W2, b2);
    combine_kernel<<<(kT * kD / 4 + 255) / 256, 256>>>(out);
}

// round 15
// speedup vs baseline: 1.0385x; 1.0385x over previous
#include <cuda_runtime.h>
#include <cuda_fp16.h>
#include <math.h>

// ---------------- problem constants ----------------
constexpr int kT   = 1024;
constexpr int kD   = 1024;
constexpr int kH   = 16;
constexpr int kDH  = 64;
constexpr int kE   = 8;
constexpr int kDFF = 4096;
constexpr int kSlots = 3072;   // 2048 assignments + per-expert pad to 128

// ---------------- device scratch ----------------
__device__ float g_x[kT * kD];
__device__ float g_q[kH * kT * kDH];
__device__ float g_kT[kH * kDH * kT];   // K transposed: [h][dh][t]
__device__ float g_v[kH * kT * kDH];
__device__ float g_attn[kT * kD];
__device__ float g_emb2[kT * kD];
__device__ float g_y[kT * kD];
__device__ __half g_h[kSlots * kDFF];   // expert hidden, fp16
__device__ float g_yo[kSlots * kD];
__device__ int   g_ids[kT * 2];
__device__ float g_gates[kT * 2];
__device__ int   g_counts[kE];
__device__ int   g_poff[kE + 1];
__device__ int   g_cursor[kE];
__device__ int   g_slot_token[kSlots];
__device__ int   g_slotpos[kT * 2];
__device__ float g_impsum[kE];

// ---------------- mma helpers ----------------
__device__ __forceinline__ void mma_f16(float c[4], const unsigned a[4], const unsigned b[2]) {
    asm volatile("mma.sync.aligned.m16n8k16.row.col.f32.f16.f16.f32 "
        "{%0,%1,%2,%3}, {%4,%5,%6,%7}, {%8,%9}, {%0,%1,%2,%3};\n"
        : "+f"(c[0]), "+f"(c[1]), "+f"(c[2]), "+f"(c[3])
        : "r"(a[0]), "r"(a[1]), "r"(a[2]), "r"(a[3]), "r"(b[0]), "r"(b[1]));
}
__device__ __forceinline__ unsigned pk2(float a, float b) {
    __half2 h = __floats2half2_rn(a, b);
    return *(unsigned*)&h;
}

// fp16 GEMM tile config: block 256 threads, tile M=128 N=128, warp tile 32x64,
// K-panel 32 (= 2 k16 MMAs), DOUBLE-BUFFERED smem (1 sync per panel).
constexpr int ASTR = 20;
constexpr int BSTR = 136;

#define GEMM16_SMEM \
    __shared__ __align__(16) unsigned As[2][128 * ASTR]; \
    __shared__ __align__(16) unsigned Bs[2][16 * BSTR];

#define GEMM16_COMPUTE(buf) \
    _Pragma("unroll") \
    for (int p0 = 0; p0 < 16; p0 += 8) { \
        unsigned bf[8][2]; \
        _Pragma("unroll") \
        for (int nt = 0; nt < 8; nt++) { \
            int n = wn * 64 + nt * 8 + (lane >> 2); \
            bf[nt][0] = Bs[buf][(p0 + (lane & 3)) * BSTR + n]; \
            bf[nt][1] = Bs[buf][(p0 + 4 + (lane & 3)) * BSTR + n]; \
        } \
        _Pragma("unroll") \
        for (int mt = 0; mt < 2; mt++) { \
            int m = wm * 32 + mt * 16 + (lane >> 2); \
            unsigned af[4]; \
            af[0] = As[buf][m * ASTR + p0 + (lane & 3)]; \
            af[1] = As[buf][(m + 8) * ASTR + p0 + (lane & 3)]; \
            af[2] = As[buf][m * ASTR + p0 + 4 + (lane & 3)]; \
            af[3] = As[buf][(m + 8) * ASTR + p0 + 4 + (lane & 3)]; \
            _Pragma("unroll") \
            for (int nt = 0; nt < 8; nt++) mma_f16(acc[mt][nt], af, bf[nt]); \
        } \
    }

#define GEMM16_STORE_REGS(buf) \
    _Pragma("unroll") \
    for (int p = 0; p < 4; p++) \
        *(uint2*)&As[buf][((tid >> 3) + p * 32) * ASTR + (tid & 7) * 2] = pa[p]; \
    _Pragma("unroll") \
    for (int p = 0; p < 2; p++) \
        *(uint4*)&Bs[buf][((tid >> 5) + p * 8) * BSTR + (tid & 31) * 4] = pb[p];

// ---------------- misc helpers ----------------
__device__ __forceinline__ float block_reduce_sum(float v) {
    __shared__ float sh[32];
    int lane = threadIdx.x & 31, w = threadIdx.x >> 5;
    #pragma unroll
    for (int o = 16; o > 0; o >>= 1) v += __shfl_xor_sync(0xffffffffu, v, o);
    if (lane == 0) sh[w] = v;
    __syncthreads();
    if (w == 0) {
        v = (lane < (int)(blockDim.x >> 5)) ? sh[lane] : 0.f;
        #pragma unroll
        for (int o = 16; o > 0; o >>= 1) v += __shfl_xor_sync(0xffffffffu, v, o);
        if (lane == 0) sh[0] = v;
    }
    __syncthreads();
    float r = sh[0];
    __syncthreads();
    return r;
}

// ---------------- LN1 (+ folded scratch reset) ----------------
__global__ void ln_kernel(const float* __restrict__ in, const float* __restrict__ g,
                          const float* __restrict__ b, float* __restrict__ out) {
    int gi = blockIdx.x * blockDim.x + threadIdx.x;
    if (gi < kSlots) g_slot_token[gi] = -1;
    if (gi < kE) { g_counts[gi] = 0; g_impsum[gi] = 0.f; }

    int row = blockIdx.x;
    const float* x = in + (size_t)row * kD;
    float s = 0.f;
    for (int i = threadIdx.x; i < kD; i += blockDim.x) s += x[i];
    float mean = block_reduce_sum(s) * (1.f / kD);
    float v = 0.f;
    for (int i = threadIdx.x; i < kD; i += blockDim.x) {
        float d = x[i] - mean; v += d * d;
    }
    float var = block_reduce_sum(v) * (1.f / kD);
    float rstd = rsqrtf(var + 1e-6f);
    float* o = out + (size_t)row * kD;
    for (int i = threadIdx.x; i < kD; i += blockDim.x)
        o[i] = (x[i] - mean) * rstd * g[i] + b[i];
}

// ---------------- fused LN2 + router ----------------
__global__ void ln2_router_kernel(const float* __restrict__ in,
                                  const float* __restrict__ g, const float* __restrict__ b,
                                  float* __restrict__ out,
                                  const float* __restrict__ Wr, const float* __restrict__ br) {
    int row = blockIdx.x;
    const float* x = in + (size_t)row * kD;
    float s = 0.f;
    for (int i = threadIdx.x; i < kD; i += blockDim.x) s += x[i];
    float mean = block_reduce_sum(s) * (1.f / kD);
    float v = 0.f;
    for (int i = threadIdx.x; i < kD; i += blockDim.x) {
        float d = x[i] - mean; v += d * d;
    }
    float var = block_reduce_sum(v) * (1.f / kD);
    float rstd = rsqrtf(var + 1e-6f);
    float* o = out + (size_t)row * kD;
    float rs[kE];
    #pragma unroll
    for (int e = 0; e < kE; e++) rs[e] = 0.f;
    for (int i = threadIdx.x; i < kD; i += blockDim.x) {
        float val = (x[i] - mean) * rstd * g[i] + b[i];
        o[i] = val;
        const float* wr = Wr + (size_t)i * kE;
        #pragma unroll
        for (int e = 0; e < kE; e++) rs[e] += val * wr[e];
    }
    #pragma unroll
    for (int e = 0; e < kE; e++) rs[e] = block_reduce_sum(rs[e]);
    if (threadIdx.x == 0) {
        float w[kE];
        float mx = -1e30f;
        #pragma unroll
        for (int e = 0; e < kE; e++) { w[e] = rs[e] + br[e]; mx = fmaxf(mx, w[e]); }
        float sum = 0.f;
        #pragma unroll
        for (int e = 0; e < kE; e++) { w[e] = __expf(w[e] - mx); sum += w[e]; }
        float inv = 1.f / sum;
        #pragma unroll
        for (int e = 0; e < kE; e++) w[e] *= inv;
        int i0 = 0;
        #pragma unroll
        for (int e = 1; e < kE; e++) if (w[e] > w[i0]) i0 = e;
        int i1 = -1;
        #pragma unroll
        for (int e = 0; e < kE; e++) if (e != i0 && (i1 < 0 || w[e] > w[i1])) i1 = e;
        float norm = w[i0] + w[i1];
        g_ids[row * 2]     = i0;
        g_ids[row * 2 + 1] = i1;
        g_gates[row * 2]     = w[i0] / norm;
        g_gates[row * 2 + 1] = w[i1] / norm;
        atomicAdd(&g_counts[i0], 1);
        atomicAdd(&g_counts[i1], 1);
        #pragma unroll
        for (int e = 0; e < kE; e++) atomicAdd(&g_impsum[e], w[e]);
    }
}

// ---------------- QKV fp16 GEMM + fused RoPE (K written transposed), M128 ----------------
__global__ __launch_bounds__(256) void qkv_kernel(
    const float* __restrict__ x,
    const float* __restrict__ WQ, const float* __restrict__ WK, const float* __restrict__ WV,
    float* __restrict__ Qo, float* __restrict__ KTo, float* __restrict__ Vo) {
    GEMM16_SMEM
    int tid = threadIdx.x, lane = tid & 31, w = tid >> 5;
    int wm = w & 3, wn = w >> 2;
    int r0 = blockIdx.x * 128;
    int n0 = blockIdx.y * 128;
    int z = blockIdx.z;
    const float* W = (z == 0) ? WQ : (z == 1) ? WK : WV;

    int bn4 = (tid & 31) * 4;
    int bh = (n0 + bn4) >> 6, be = (n0 + bn4) & 63;
    uint2 pa[4];
    uint4 pb[2];

    #define QKV_LOAD_REGS(k0_) { \
        _Pragma("unroll") \
        for (int p = 0; p < 4; p++) { \
            int m = (tid >> 3) + p * 32; \
            float4 v = *(const float4*)&x[(size_t)(r0 + m) * kD + (k0_) + (tid & 7) * 4]; \
            pa[p].x = pk2(v.x, v.y); pa[p].y = pk2(v.z, v.w); \
        } \
        _Pragma("unroll") \
        for (int p = 0; p < 2; p++) { \
            int kp = (tid >> 5) + p * 8; \
            const float* b0p = &W[((size_t)bh * kD + (k0_) + 2 * kp) * kDH + be]; \
            float4 r0v = *(const float4*)b0p; \
            float4 r1v = *(const float4*)(b0p + kDH); \
            pb[p].x = pk2(r0v.x, r1v.x); pb[p].y = pk2(r0v.y, r1v.y); \
            pb[p].z = pk2(r0v.z, r1v.z); pb[p].w = pk2(r0v.w, r1v.w); \
        } \
    }

    float acc[2][8][4] = {};
    QKV_LOAD_REGS(0)
    GEMM16_STORE_REGS(0)
    __syncthreads();
    for (int k0 = 0, i = 0; k0 < kD; k0 += 32, i++) {
        if (k0 + 32 < kD) QKV_LOAD_REGS(k0 + 32)
        GEMM16_COMPUTE(i & 1)
        if (k0 + 32 < kD) GEMM16_STORE_REGS((i + 1) & 1)
        __syncthreads();
    }
    #undef QKV_LOAD_REGS

    #pragma unroll
    for (int mt = 0; mt < 2; mt++) {
        #pragma unroll
        for (int nt = 0; nt < 8; nt++) {
            int n = n0 + wn * 64 + nt * 8 + (lane & 3) * 2;
            int h = n >> 6, e = n & 63;
            #pragma unroll
            for (int half = 0; half < 2; half++) {
                int t = r0 + wm * 32 + mt * 16 + (lane >> 2) + half * 8;
                float v0 = acc[mt][nt][half * 2 + 0];
                float v1 = acc[mt][nt][half * 2 + 1];
                if (z < 2) {
                    int p = e >> 1;
                    float theta = exp2f(-(float)p * (13.287712379549449f / 32.f));
                    float sn, cs;
                    sincosf((float)t * theta, &sn, &cs);
                    float w0 = v0 * cs - v1 * sn;
                    float w1 = v1 * cs + v0 * sn;
                    v0 = w0; v1 = w1;
                }
                if (z == 1) {
                    KTo[((size_t)h * kDH + e) * kT + t]     = v0;
                    KTo[((size_t)h * kDH + e + 1) * kT + t] = v1;
                } else {
                    float* O = (z == 0) ? Qo : Vo;
                    float2 r2 = { v0, v1 };
                    *(float2*)&O[((size_t)h * kT + t) * kDH + e] = r2;
                }
            }
        }
    }
}

// ---------------- flash attention (fp16 mma): block = (64 q-rows, head), 4 warps ----------------
// QPs: Q then P, [row][k-pair], 64 x 36 uints (half2 pairs along k)
// Ks:  [dh-pair][key], 32 x 72 uints (half2 = K[2p][key], K[2p+1][key])
// Vs:  [key-pair][dh], 32 x 72 uints (half2 = V[2k][dh], V[2k+1][dh])
constexpr int AQP = 36;
constexpr int AKV = 72;

__global__ __launch_bounds__(128) void attn_kernel(
    const float* __restrict__ Q, const float* __restrict__ KTr,
    const float* __restrict__ V, float* __restrict__ A) {
    __shared__ __align__(16) unsigned QPs[64 * AQP];
    __shared__ __align__(16) unsigned Ks[32 * AKV];
    __shared__ __align__(16) unsigned Vs[32 * AKV];
    int tid = threadIdx.x, lane = tid & 31, w = tid >> 5;
    int h = blockIdx.y;
    int qt = (int)gridDim.x - 1 - (int)blockIdx.x;   // heavy tiles first
    int q0 = qt * 64;
    const float* Qh  = Q   + ((size_t)h * kT + q0) * kDH;
    const float* KTh = KTr + (size_t)h * kDH * kT;
    const float* Vh  = V   + (size_t)h * kT * kDH;

    // stage Q tile (fp16 pairs along dh)
    #pragma unroll
    for (int it = 0; it < 4; it++) {
        int idx = tid + it * 128;
        int m = idx >> 3, c4 = (idx & 7) * 4;
        const float* qp = &Qh[(size_t)m * kDH + c4 * 2];
        float4 v1 = *(const float4*)qp;
        float4 v2 = *(const float4*)(qp + 4);
        uint4 u = { pk2(v1.x, v1.y), pk2(v1.z, v1.w), pk2(v2.x, v2.y), pk2(v2.z, v2.w) };
        *(uint4*)&QPs[m * AQP + c4] = u;
    }
    __syncthreads();
    unsigned qf[4][4];
    {
        int m = w * 16 + (lane >> 2);
        #pragma unroll
        for (int kk = 0; kk < 4; kk++) {
            qf[kk][0] = QPs[m * AQP + kk * 8 + (lane & 3)];
            qf[kk][1] = QPs[(m + 8) * AQP + kk * 8 + (lane & 3)];
            qf[kk][2] = QPs[m * AQP + kk * 8 + 4 + (lane & 3)];
            qf[kk][3] = QPs[(m + 8) * AQP + kk * 8 + 4 + (lane & 3)];
        }
    }

    float acc_o[8][4] = {};
    float m0 = -1e30f, m1 = -1e30f, l0 = 0.f, l1 = 0.f;

    for (int kt = 0; kt <= qt; kt++) {
        int k0 = kt * 64;
        __syncthreads();   // previous tile's reads done (and Q frag reads on iter 0)
        // K tile: Ks[dh-pair][key]
        #pragma unroll
        for (int it = 0; it < 4; it++) {
            int idx = tid + it * 128;
            int p = idx >> 4, key4 = (idx & 15) * 4;
            const float* kp0 = &KTh[(size_t)(2 * p) * kT + k0 + key4];
            float4 r0v = *(const float4*)kp0;
            float4 r1v = *(const float4*)(kp0 + kT);
            uint4 u = { pk2(r0v.x, r1v.x), pk2(r0v.y, r1v.y), pk2(r0v.z, r1v.z), pk2(r0v.w, r1v.w) };
            *(uint4*)&Ks[p * AKV + key4] = u;
        }
        // V tile: Vs[key-pair][dh]
        #pragma unroll
        for (int it = 0; it < 4; it++) {
            int idx = tid + it * 128;
            int kp = idx >> 4, dh4 = (idx & 15) * 4;
            const float* vp = &Vh[(size_t)(k0 + 2 * kp) * kDH + dh4];
            float4 r0v = *(const float4*)vp;
            float4 r1v = *(const float4*)(vp + kDH);
            uint4 u = { pk2(r0v.x, r1v.x), pk2(r0v.y, r1v.y), pk2(r0v.z, r1v.z), pk2(r0v.w, r1v.w) };
            *(uint4*)&Vs[kp * AKV + dh4] = u;
        }
        __syncthreads();

        // S = Q @ K^T (4 k16 steps over dh=64)
        float s_acc[8][4] = {};
        #pragma unroll
        for (int kk = 0; kk < 4; kk++) {
            #pragma unroll
            for (int nt = 0; nt < 8; nt++) {
                unsigned bf[2];
                bf[0] = Ks[(kk * 8 + (lane & 3)) * AKV + nt * 8 + (lane >> 2)];
                bf[1] = Ks[(kk * 8 + 4 + (lane & 3)) * AKV + nt * 8 + (lane >> 2)];
                mma_f16(s_acc[nt], qf[kk], bf);
            }
        }

        float rm0 = -1e30f, rm1 = -1e30f;
        int gq0 = q0 + w * 16 + (lane >> 2);
        #pragma unroll
        for (int nt = 0; nt < 8; nt++) {
            #pragma unroll
            for (int c = 0; c < 4; c++) {
                float v = s_acc[nt][c] * 0.125f;
                if (kt == qt) {
                    int key = k0 + nt * 8 + 2 * (lane & 3) + (c & 1);
                    int gq = gq0 + (c >> 1) * 8;
                    if (key > gq) v = -1e30f;
                }
                s_acc[nt][c] = v;
                if ((c >> 1) == 0) rm0 = fmaxf(rm0, v); else rm1 = fmaxf(rm1, v);
            }
        }
        #pragma unroll
        for (int o = 1; o <= 2; o <<= 1) {
            rm0 = fmaxf(rm0, __shfl_xor_sync(0xffffffffu, rm0, o));
            rm1 = fmaxf(rm1, __shfl_xor_sync(0xffffffffu, rm1, o));
        }
        float nm0 = fmaxf(m0, rm0), nm1 = fmaxf(m1, rm1);
        float sc0 = __expf(m0 - nm0), sc1 = __expf(m1 - nm1);
        m0 = nm0; m1 = nm1;

        // P = exp(S - m); store fp16 pairs along keys
        float rs0 = 0.f, rs1 = 0.f;
        int prow = w * 16 + (lane >> 2);
        #pragma unroll
        for (int nt = 0; nt < 8; nt++) {
            float p0 = __expf(s_acc[nt][0] - nm0);
            float p1 = __expf(s_acc[nt][1] - nm0);
            float p2 = __expf(s_acc[nt][2] - nm1);
            float p3 = __expf(s_acc[nt][3] - nm1);
            rs0 += p0 + p1; rs1 += p2 + p3;
            QPs[prow * AQP + nt * 4 + (lane & 3)]       = pk2(p0, p1);
            QPs[(prow + 8) * AQP + nt * 4 + (lane & 3)] = pk2(p2, p3);
        }
        #pragma unroll
        for (int o = 1; o <= 2; o <<= 1) {
            rs0 += __shfl_xor_sync(0xffffffffu, rs0, o);
            rs1 += __shfl_xor_sync(0xffffffffu, rs1, o);
        }
        l0 = l0 * sc0 + rs0;
        l1 = l1 * sc1 + rs1;
        #pragma unroll
        for (int nt = 0; nt < 8; nt++) {
            acc_o[nt][0] *= sc0; acc_o[nt][1] *= sc0;
            acc_o[nt][2] *= sc1; acc_o[nt][3] *= sc1;
        }
        __syncwarp();

        // O += P @ V (4 k16 steps over 64 keys)
        #pragma unroll
        for (int kk = 0; kk < 4; kk++) {
            unsigned pf[4];
            int m = w * 16 + (lane >> 2);
            pf[0] = QPs[m * AQP + kk * 8 + (lane & 3)];
            pf[1] = QPs[(m + 8) * AQP + kk * 8 + (lane & 3)];
            pf[2] = QPs[m * AQP + kk * 8 + 4 + (lane & 3)];
            pf[3] = QPs[(m + 8) * AQP + kk * 8 + 4 + (lane & 3)];
            #pragma unroll
            for (int nt = 0; nt < 8; nt++) {
                unsigned bf[2];
                bf[0] = Vs[(kk * 8 + (lane & 3)) * AKV + nt * 8 + (lane >> 2)];
                bf[1] = Vs[(kk * 8 + 4 + (lane & 3)) * AKV + nt * 8 + (lane >> 2)];
                mma_f16(acc_o[nt], pf, bf);
            }
        }
    }

    float inv0 = 1.f / l0, inv1 = 1.f / l1;
    int gq0 = q0 + w * 16 + (lane >> 2);
    #pragma unroll
    for (int nt = 0; nt < 8; nt++) {
        int col = h * kDH + nt * 8 + 2 * (lane & 3);
        float2 r0 = { acc_o[nt][0] * inv0, acc_o[nt][1] * inv0 };
        float2 r1 = { acc_o[nt][2] * inv1, acc_o[nt][3] * inv1 };
        *(float2*)&A[(size_t)gq0 * kD + col] = r0;
        *(float2*)&A[(size_t)(gq0 + 8) * kD + col] = r1;
    }
}

// ---------------- proj fp16 GEMM + residual, M128 ----------------
__global__ __launch_bounds__(256) void proj_kernel(
    const float* __restrict__ A, const float* __restrict__ W,
    const float* __restrict__ bias, const float* __restrict__ emb,
    float* __restrict__ out) {
    GEMM16_SMEM
    int tid = threadIdx.x, lane = tid & 31, w = tid >> 5;
    int wm = w & 3, wn = w >> 2;
    int r0 = blockIdx.x * 128;
    int n0 = blockIdx.y * 128;

    uint2 pa[4];
    uint4 pb[2];

    #define PROJ_LOAD_REGS(k0_) { \
        _Pragma("unroll") \
        for (int p = 0; p < 4; p++) { \
            int m = (tid >> 3) + p * 32; \
            float4 v = *(const float4*)&A[(size_t)(r0 + m) * kD + (k0_) + (tid & 7) * 4]; \
            pa[p].x = pk2(v.x, v.y); pa[p].y = pk2(v.z, v.w); \
        } \
        _Pragma("unroll") \
        for (int p = 0; p < 2; p++) { \
            int kp = (tid >> 5) + p * 8; \
            const float* b0p = &W[(size_t)((k0_) + 2 * kp) * kD + n0 + (tid & 31) * 4]; \
            float4 r0v = *(const float4*)b0p; \
            float4 r1v = *(const float4*)(b0p + kD); \
            pb[p].x = pk2(r0v.x, r1v.x); pb[p].y = pk2(r0v.y, r1v.y); \
            pb[p].z = pk2(r0v.z, r1v.z); pb[p].w = pk2(r0v.w, r1v.w); \
        } \
    }

    float acc[2][8][4] = {};
    PROJ_LOAD_REGS(0)
    GEMM16_STORE_REGS(0)
    __syncthreads();
    for (int k0 = 0, i = 0; k0 < kD; k0 += 32, i++) {
        if (k0 + 32 < kD) PROJ_LOAD_REGS(k0 + 32)
        GEMM16_COMPUTE(i & 1)
        if (k0 + 32 < kD) GEMM16_STORE_REGS((i + 1) & 1)
        __syncthreads();
    }
    #undef PROJ_LOAD_REGS

    #pragma unroll
    for (int mt = 0; mt < 2; mt++) {
        #pragma unroll
        for (int nt = 0; nt < 8; nt++) {
            int c = n0 + wn * 64 + nt * 8 + (lane & 3) * 2;
            #pragma unroll
            for (int half = 0; half < 2; half++) {
                int r = r0 + wm * 32 + mt * 16 + (lane >> 2) + half * 8;
                float2 e2 = *(const float2*)&emb[(size_t)r * kD + c];
                float2 r2;
                r2.x = e2.x + acc[mt][nt][half * 2 + 0] + bias[c];
                r2.y = e2.y + acc[mt][nt][half * 2 + 1] + bias[c + 1];
                *(float2*)&out[(size_t)r * kD + c] = r2;
            }
        }
    }
}

// ---------------- fused offsets + aux + scatter (single block) ----------------
__global__ void offsets_scatter_kernel(float* __restrict__ out, int out_size) {
    int tid = threadIdx.x;
    if (tid == 0) {
        int off = 0;
        g_poff[0] = 0;
        for (int e = 0; e < kE; e++) {
            int pc = (g_counts[e] + 127) & ~127;
            off += pc;
            g_poff[e + 1] = off;
            g_cursor[e] = g_poff[e];
        }
        float aux = 0.f;
        for (int e = 0; e < kE; e++) {
            float imp = g_impsum[e] / (float)kT;
            float dlt = imp - 1.f / (float)kE;
            aux += dlt * dlt;
        }
        aux *= 1.f / (float)kE;
        if (out_size > kT * kD) out[kT * kD] = aux;
    }
    __syncthreads();
    for (int i = tid; i < kT * 2; i += blockDim.x) {
        int e = g_ids[i];
        int pos = atomicAdd(&g_cursor[e], 1);
        g_slot_token[pos] = i >> 1;
        g_slotpos[i] = pos;
    }
}

// ---------------- F1 fp16 GEMM: h = relu(...) -> fp16 out, M128 ----------------
__global__ __launch_bounds__(256) void f1_kernel(
    const float* __restrict__ y, const float* __restrict__ W1,
    const float* __restrict__ b1) {
    GEMM16_SMEM
    __shared__ int tok[128];
    __shared__ int sh_total, sh_e;
    int tid = threadIdx.x, lane = tid & 31, w = tid >> 5;
    int wm = w & 3, wn = w >> 2;
    int s0 = blockIdx.x * 128;
    if (tid == 0) {
        sh_total = g_poff[kE];
        int e = 0;
        while (e < kE - 1 && s0 >= g_poff[e + 1]) e++;
        sh_e = e;
    }
    if (tid < 128) tok[tid] = g_slot_token[s0 + tid];
    __syncthreads();
    if (s0 >= sh_total) return;
    int e = sh_e;
    const float* W = W1 + (size_t)e * kD * kDFF;
    int f0 = blockIdx.y * 128;
    int atok[4];
    #pragma unroll
    for (int p = 0; p < 4; p++) atok[p] = tok[(tid >> 3) + p * 32];

    uint2 pa[4];
    uint4 pb[2];

    #define F1_LOAD_REGS(k0_) { \
        _Pragma("unroll") \
        for (int p = 0; p < 4; p++) { \
            int t = atok[p]; \
            if (t >= 0) { \
                float4 v = *(const float4*)&y[(size_t)t * kD + (k0_) + (tid & 7) * 4]; \
                pa[p].x = pk2(v.x, v.y); pa[p].y = pk2(v.z, v.w); \
            } else { pa[p].x = 0u; pa[p].y = 0u; } \
        } \
        _Pragma("unroll") \
        for (int p = 0; p < 2; p++) { \
            int kp = (tid >> 5) + p * 8; \
            const float* b0p = &W[(size_t)((k0_) + 2 * kp) * kDFF + f0 + (tid & 31) * 4]; \
            float4 r0v = *(const float4*)b0p; \
            float4 r1v = *(const float4*)(b0p + kDFF); \
            pb[p].x = pk2(r0v.x, r1v.x); pb[p].y = pk2(r0v.y, r1v.y); \
            pb[p].z = pk2(r0v.z, r1v.z); pb[p].w = pk2(r0v.w, r1v.w); \
        } \
    }

    float acc[2][8][4] = {};
    F1_LOAD_REGS(0)
    GEMM16_STORE_REGS(0)
    __syncthreads();
    for (int k0 = 0, i = 0; k0 < kD; k0 += 32, i++) {
        if (k0 + 32 < kD) F1_LOAD_REGS(k0 + 32)
        GEMM16_COMPUTE(i & 1)
        if (k0 + 32 < kD) GEMM16_STORE_REGS((i + 1) & 1)
        __syncthreads();
    }
    #undef F1_LOAD_REGS

    #pragma unroll
    for (int mt = 0; mt < 2; mt++) {
        #pragma unroll
        for (int nt = 0; nt < 8; nt++) {
            int c = f0 + wn * 64 + nt * 8 + (lane & 3) * 2;
            float bb0 = b1[(size_t)e * kDFF + c];
            float bb1 = b1[(size_t)e * kDFF + c + 1];
            #pragma unroll
            for (int half = 0; half < 2; half++) {
                int r = s0 + wm * 32 + mt * 16 + (lane >> 2) + half * 8;
                float h0 = fmaxf(acc[mt][nt][half * 2 + 0] + bb0, 0.f);
                float h1 = fmaxf(acc[mt][nt][half * 2 + 1] + bb1, 0.f);
                __half2 hv = __floats2half2_rn(h0, h1);
                *(__half2*)&g_h[(size_t)r * kDFF + c] = hv;
            }
        }
    }
}

// ---------------- F2 fp16 GEMM: yo = h @ W2[e] + b2[e], M128 ----------------
__global__ __launch_bounds__(256) void f2_kernel(
    const float* __restrict__ W2, const float* __restrict__ b2) {
    GEMM16_SMEM
    __shared__ int sh_total, sh_e;
    int tid = threadIdx.x, lane = tid & 31, w = tid >> 5;
    int wm = w & 3, wn = w >> 2;
    int s0 = blockIdx.x * 128;
    if (tid == 0) {
        sh_total = g_poff[kE];
        int e = 0;
        while (e < kE - 1 && s0 >= g_poff[e + 1]) e++;
        sh_e = e;
    }
    __syncthreads();
    if (s0 >= sh_total) return;
    int e = sh_e;
    const float* W = W2 + (size_t)e * kDFF * kD;
    int c0 = blockIdx.y * 128;

    uint2 pa[4];
    uint4 pb[2];

    #define F2_LOAD_REGS(k0_) { \
        _Pragma("unroll") \
        for (int p = 0; p < 4; p++) { \
            int m = (tid >> 3) + p * 32; \
            pa[p] = *(const uint2*)&g_h[(size_t)(s0 + m) * kDFF + (k0_) + (tid & 7) * 4]; \
        } \
        _Pragma("unroll") \
        for (int p = 0; p < 2; p++) { \
            int kp = (tid >> 5) + p * 8; \
            const float* b0p = &W[(size_t)((k0_) + 2 * kp) * kD + c0 + (tid & 31) * 4]; \
            float4 r0v = *(const float4*)b0p; \
            float4 r1v = *(const float4*)(b0p + kD); \
            pb[p].x = pk2(r0v.x, r1v.x); pb[p].y = pk2(r0v.y, r1v.y); \
            pb[p].z = pk2(r0v.z, r1v.z); pb[p].w = pk2(r0v.w, r1v.w); \
        } \
    }

    float acc[2][8][4] = {};
    F2_LOAD_REGS(0)
    GEMM16_STORE_REGS(0)
    __syncthreads();
    for (int k0 = 0, i = 0; k0 < kDFF; k0 += 32, i++) {
        if (k0 + 32 < kDFF) F2_LOAD_REGS(k0 + 32)
        GEMM16_COMPUTE(i & 1)
        if (k0 + 32 < kDFF) GEMM16_STORE_REGS((i + 1) & 1)
        __syncthreads();
    }
    #undef F2_LOAD_REGS

    #pragma unroll
    for (int mt = 0; mt < 2; mt++) {
        #pragma unroll
        for (int nt = 0; nt < 8; nt++) {
            int c = c0 + wn * 64 + nt * 8 + (lane & 3) * 2;
            float bb0 = b2[(size_t)e * kD + c];
            float bb1 = b2[(size_t)e * kD + c + 1];
            #pragma unroll
            for (int half = 0; half < 2; half++) {
                int r = s0 + wm * 32 + mt * 16 + (lane >> 2) + half * 8;
                float2 r2;
                r2.x = acc[mt][nt][half * 2 + 0] + bb0;
                r2.y = acc[mt][nt][half * 2 + 1] + bb1;
                *(float2*)&g_yo[(size_t)r * kD + c] = r2;
            }
        }
    }
}

// ---------------- combine ----------------
__global__ void combine_kernel(float* __restrict__ out) {
    int idx4 = blockIdx.x * blockDim.x + threadIdx.x;
    if (idx4 >= kT * kD / 4) return;
    int idx = idx4 * 4;
    int n = idx >> 10;
    int d = idx & (kD - 1);
    int p0 = g_slotpos[n * 2], p1 = g_slotpos[n * 2 + 1];
    float g0 = g_gates[n * 2], g1 = g_gates[n * 2 + 1];
    float4 base = *(const float4*)&g_emb2[idx];
    float4 y0 = *(const float4*)&g_yo[(size_t)p0 * kD + d];
    float4 y1 = *(const float4*)&g_yo[(size_t)p1 * kD + d];
    float4 r;
    r.x = base.x + g0 * y0.x + g1 * y1.x;
    r.y = base.y + g0 * y0.y + g1 * y1.y;
    r.z = base.z + g0 * y0.z + g1 * y1.z;
    r.w = base.w + g0 * y0.w + g1 * y1.w;
    *(float4*)&out[idx] = r;
}

// ---------------- launch ----------------
extern "C" void kernel_launch(void* const* d_in, const int* in_sizes, int n_in,
                              void* d_out, int out_size) {
    const float* emb    = (const float*)d_in[0];
    const float* gamma1 = (const float*)d_in[1];
    const float* beta1  = (const float*)d_in[2];
    const float* WQ     = (const float*)d_in[3];
    const float* WK     = (const float*)d_in[4];
    const float* WV     = (const float*)d_in[5];
    const float* Wproj  = (const float*)d_in[6];
    const float* bproj  = (const float*)d_in[7];
    const float* gamma2 = (const float*)d_in[8];
    const float* beta2  = (const float*)d_in[9];
    const float* Wr     = (const float*)d_in[10];
    const float* br     = (const float*)d_in[11];
    const float* W1     = (const float*)d_in[12];
    const float* b1     = (const float*)d_in[13];
    const float* W2     = (const float*)d_in[14];
    const float* b2     = (const float*)d_in[15];
    float* out = (float*)d_out;

    float* gx;    cudaGetSymbolAddress((void**)&gx, g_x);
    float* gq;    cudaGetSymbolAddress((void**)&gq, g_q);
    float* gkT;   cudaGetSymbolAddress((void**)&gkT, g_kT);
    float* gv;    cudaGetSymbolAddress((void**)&gv, g_v);
    float* gattn; cudaGetSymbolAddress((void**)&gattn, g_attn);
    float* gemb2; cudaGetSymbolAddress((void**)&gemb2, g_emb2);
    float* gy;    cudaGetSymbolAddress((void**)&gy, g_y);

    ln_kernel<<<kT, 256>>>(emb, gamma1, beta1, gx);
    qkv_kernel<<<dim3(kT / 128, (kH * kDH) / 128, 3), 256>>>(gx, WQ, WK, WV, gq, gkT, gv);
    attn_kernel<<<dim3(kT / 64, kH), 128>>>(gq, gkT, gv, gattn);
    proj_kernel<<<dim3(kT / 128, kD / 128), 256>>>(gattn, Wproj, bproj, emb, gemb2);
    ln2_router_kernel<<<kT, 256>>>(gemb2, gamma2, beta2, gy, Wr, br);
    offsets_scatter_kernel<<<1, 1024>>>(out, out_size);
    f1_kernel<<<dim3(kSlots / 128, kDFF / 128), 256>>>(gy, W1, b1);
    f2_kernel<<<dim3(kSlots / 128, kD / 128), 256>>>(W2, b2);
    combine_kernel<<<(kT * kD / 4 + 255) / 256, 256>>>(out);
}

// round 16
// speedup vs baseline: 1.0492x; 1.0103x over previous
#include <cuda_runtime.h>
#include <cuda_fp16.h>
#include <math.h>

// ---------------- problem constants ----------------
constexpr int kT   = 1024;
constexpr int kD   = 1024;
constexpr int kH   = 16;
constexpr int kDH  = 64;
constexpr int kE   = 8;
constexpr int kDFF = 4096;
constexpr int kSlots = 3072;   // 2048 assignments + per-expert pad to 128

// ---------------- device scratch ----------------
__device__ __half g_x[kT * kD];          // LN1 out (fp16 - feeds qkv MMA A)
__device__ __half g_q[kH * kT * kDH];    // fp16 - feeds attn MMA
__device__ __half g_kT[kH * kDH * kT];   // K transposed [h][dh][t], fp16
__device__ __half g_v[kH * kT * kDH];    // fp16
__device__ __half g_attn[kT * kD];       // fp16 - feeds proj MMA A
__device__ float  g_emb2[kT * kD];       // fp32 (residual -> output)
__device__ __half g_y[kT * kD];          // LN2 out, fp16 - feeds f1 MMA A
__device__ __half g_h[kSlots * kDFF];    // expert hidden, fp16
__device__ float  g_yo[kSlots * kD];     // fp32 (-> output)
__device__ int   g_ids[kT * 2];
__device__ float g_gates[kT * 2];
__device__ int   g_counts[kE];
__device__ int   g_poff[kE + 1];
__device__ int   g_cursor[kE];
__device__ int   g_slot_token[kSlots];
__device__ int   g_slotpos[kT * 2];
__device__ float g_impsum[kE];

// ---------------- mma helpers ----------------
__device__ __forceinline__ void mma_f16(float c[4], const unsigned a[4], const unsigned b[2]) {
    asm volatile("mma.sync.aligned.m16n8k16.row.col.f32.f16.f16.f32 "
        "{%0,%1,%2,%3}, {%4,%5,%6,%7}, {%8,%9}, {%0,%1,%2,%3};\n"
        : "+f"(c[0]), "+f"(c[1]), "+f"(c[2]), "+f"(c[3])
        : "r"(a[0]), "r"(a[1]), "r"(a[2]), "r"(a[3]), "r"(b[0]), "r"(b[1]));
}
__device__ __forceinline__ unsigned pk2(float a, float b) {
    __half2 h = __floats2half2_rn(a, b);
    return *(unsigned*)&h;
}

// fp16 GEMM tile config: block 256 threads, tile M=128 N=128, warp tile 32x64,
// K-panel 32 (= 2 k16 MMAs), DOUBLE-BUFFERED smem (1 sync per panel).
constexpr int ASTR = 20;
constexpr int BSTR = 136;

#define GEMM16_SMEM \
    __shared__ __align__(16) unsigned As[2][128 * ASTR]; \
    __shared__ __align__(16) unsigned Bs[2][16 * BSTR];

#define GEMM16_COMPUTE(buf) \
    _Pragma("unroll") \
    for (int p0 = 0; p0 < 16; p0 += 8) { \
        unsigned bf[8][2]; \
        _Pragma("unroll") \
        for (int nt = 0; nt < 8; nt++) { \
            int n = wn * 64 + nt * 8 + (lane >> 2); \
            bf[nt][0] = Bs[buf][(p0 + (lane & 3)) * BSTR + n]; \
            bf[nt][1] = Bs[buf][(p0 + 4 + (lane & 3)) * BSTR + n]; \
        } \
        _Pragma("unroll") \
        for (int mt = 0; mt < 2; mt++) { \
            int m = wm * 32 + mt * 16 + (lane >> 2); \
            unsigned af[4]; \
            af[0] = As[buf][m * ASTR + p0 + (lane & 3)]; \
            af[1] = As[buf][(m + 8) * ASTR + p0 + (lane & 3)]; \
            af[2] = As[buf][m * ASTR + p0 + 4 + (lane & 3)]; \
            af[3] = As[buf][(m + 8) * ASTR + p0 + 4 + (lane & 3)]; \
            _Pragma("unroll") \
            for (int nt = 0; nt < 8; nt++) mma_f16(acc[mt][nt], af, bf[nt]); \
        } \
    }

#define GEMM16_STORE_REGS(buf) \
    _Pragma("unroll") \
    for (int p = 0; p < 4; p++) \
        *(uint2*)&As[buf][((tid >> 3) + p * 32) * ASTR + (tid & 7) * 2] = pa[p]; \
    _Pragma("unroll") \
    for (int p = 0; p < 2; p++) \
        *(uint4*)&Bs[buf][((tid >> 5) + p * 8) * BSTR + (tid & 31) * 4] = pb[p];

// ---------------- misc helpers ----------------
__device__ __forceinline__ float block_reduce_sum(float v) {
    __shared__ float sh[32];
    int lane = threadIdx.x & 31, w = threadIdx.x >> 5;
    #pragma unroll
    for (int o = 16; o > 0; o >>= 1) v += __shfl_xor_sync(0xffffffffu, v, o);
    if (lane == 0) sh[w] = v;
    __syncthreads();
    if (w == 0) {
        v = (lane < (int)(blockDim.x >> 5)) ? sh[lane] : 0.f;
        #pragma unroll
        for (int o = 16; o > 0; o >>= 1) v += __shfl_xor_sync(0xffffffffu, v, o);
        if (lane == 0) sh[0] = v;
    }
    __syncthreads();
    float r = sh[0];
    __syncthreads();
    return r;
}

// ---------------- LN1 (+ folded scratch reset), fp16 out ----------------
__global__ void ln_kernel(const float* __restrict__ in, const float* __restrict__ g,
                          const float* __restrict__ b, __half* __restrict__ out) {
    int gi = blockIdx.x * blockDim.x + threadIdx.x;
    if (gi < kSlots) g_slot_token[gi] = -1;
    if (gi < kE) { g_counts[gi] = 0; g_impsum[gi] = 0.f; }

    int row = blockIdx.x;
    const float* x = in + (size_t)row * kD;
    float s = 0.f;
    for (int i = threadIdx.x; i < kD; i += blockDim.x) s += x[i];
    float mean = block_reduce_sum(s) * (1.f / kD);
    float v = 0.f;
    for (int i = threadIdx.x; i < kD; i += blockDim.x) {
        float d = x[i] - mean; v += d * d;
    }
    float var = block_reduce_sum(v) * (1.f / kD);
    float rstd = rsqrtf(var + 1e-6f);
    __half* o = out + (size_t)row * kD;
    for (int i = threadIdx.x * 2; i < kD; i += blockDim.x * 2) {
        float v0 = (x[i] - mean) * rstd * g[i] + b[i];
        float v1 = (x[i + 1] - mean) * rstd * g[i + 1] + b[i + 1];
        *(__half2*)&o[i] = __floats2half2_rn(v0, v1);
    }
}

// ---------------- fused LN2 + router, fp16 y out ----------------
__global__ void ln2_router_kernel(const float* __restrict__ in,
                                  const float* __restrict__ g, const float* __restrict__ b,
                                  __half* __restrict__ out,
                                  const float* __restrict__ Wr, const float* __restrict__ br) {
    int row = blockIdx.x;
    const float* x = in + (size_t)row * kD;
    float s = 0.f;
    for (int i = threadIdx.x; i < kD; i += blockDim.x) s += x[i];
    float mean = block_reduce_sum(s) * (1.f / kD);
    float v = 0.f;
    for (int i = threadIdx.x; i < kD; i += blockDim.x) {
        float d = x[i] - mean; v += d * d;
    }
    float var = block_reduce_sum(v) * (1.f / kD);
    float rstd = rsqrtf(var + 1e-6f);
    __half* o = out + (size_t)row * kD;
    float rs[kE];
    #pragma unroll
    for (int e = 0; e < kE; e++) rs[e] = 0.f;
    for (int i = threadIdx.x * 2; i < kD; i += blockDim.x * 2) {
        float v0 = (x[i] - mean) * rstd * g[i] + b[i];
        float v1 = (x[i + 1] - mean) * rstd * g[i + 1] + b[i + 1];
        *(__half2*)&o[i] = __floats2half2_rn(v0, v1);
        const float* wr0 = Wr + (size_t)i * kE;
        #pragma unroll
        for (int e = 0; e < kE; e++) rs[e] += v0 * wr0[e] + v1 * wr0[kE + e];
    }
    #pragma unroll
    for (int e = 0; e < kE; e++) rs[e] = block_reduce_sum(rs[e]);
    if (threadIdx.x == 0) {
        float w[kE];
        float mx = -1e30f;
        #pragma unroll
        for (int e = 0; e < kE; e++) { w[e] = rs[e] + br[e]; mx = fmaxf(mx, w[e]); }
        float sum = 0.f;
        #pragma unroll
        for (int e = 0; e < kE; e++) { w[e] = __expf(w[e] - mx); sum += w[e]; }
        float inv = 1.f / sum;
        #pragma unroll
        for (int e = 0; e < kE; e++) w[e] *= inv;
        int i0 = 0;
        #pragma unroll
        for (int e = 1; e < kE; e++) if (w[e] > w[i0]) i0 = e;
        int i1 = -1;
        #pragma unroll
        for (int e = 0; e < kE; e++) if (e != i0 && (i1 < 0 || w[e] > w[i1])) i1 = e;
        float norm = w[i0] + w[i1];
        g_ids[row * 2]     = i0;
        g_ids[row * 2 + 1] = i1;
        g_gates[row * 2]     = w[i0] / norm;
        g_gates[row * 2 + 1] = w[i1] / norm;
        atomicAdd(&g_counts[i0], 1);
        atomicAdd(&g_counts[i1], 1);
        #pragma unroll
        for (int e = 0; e < kE; e++) atomicAdd(&g_impsum[e], w[e]);
    }
}

// ---------------- QKV fp16 GEMM + fused RoPE (K written transposed), M128 ----------------
__global__ __launch_bounds__(256) void qkv_kernel(
    const __half* __restrict__ x,
    const float* __restrict__ WQ, const float* __restrict__ WK, const float* __restrict__ WV,
    __half* __restrict__ Qo, __half* __restrict__ KTo, __half* __restrict__ Vo) {
    GEMM16_SMEM
    int tid = threadIdx.x, lane = tid & 31, w = tid >> 5;
    int wm = w & 3, wn = w >> 2;
    int r0 = blockIdx.x * 128;
    int n0 = blockIdx.y * 128;
    int z = blockIdx.z;
    const float* W = (z == 0) ? WQ : (z == 1) ? WK : WV;

    int bn4 = (tid & 31) * 4;
    int bh = (n0 + bn4) >> 6, be = (n0 + bn4) & 63;
    uint2 pa[4];
    uint4 pb[2];

    #define QKV_LOAD_REGS(k0_) { \
        _Pragma("unroll") \
        for (int p = 0; p < 4; p++) { \
            int m = (tid >> 3) + p * 32; \
            pa[p] = *(const uint2*)&x[(size_t)(r0 + m) * kD + (k0_) + (tid & 7) * 4]; \
        } \
        _Pragma("unroll") \
        for (int p = 0; p < 2; p++) { \
            int kp = (tid >> 5) + p * 8; \
            const float* b0p = &W[((size_t)bh * kD + (k0_) + 2 * kp) * kDH + be]; \
            float4 r0v = *(const float4*)b0p; \
            float4 r1v = *(const float4*)(b0p + kDH); \
            pb[p].x = pk2(r0v.x, r1v.x); pb[p].y = pk2(r0v.y, r1v.y); \
            pb[p].z = pk2(r0v.z, r1v.z); pb[p].w = pk2(r0v.w, r1v.w); \
        } \
    }

    float acc[2][8][4] = {};
    QKV_LOAD_REGS(0)
    GEMM16_STORE_REGS(0)
    __syncthreads();
    for (int k0 = 0, i = 0; k0 < kD; k0 += 32, i++) {
        if (k0 + 32 < kD) QKV_LOAD_REGS(k0 + 32)
        GEMM16_COMPUTE(i & 1)
        if (k0 + 32 < kD) GEMM16_STORE_REGS((i + 1) & 1)
        __syncthreads();
    }
    #undef QKV_LOAD_REGS

    #pragma unroll
    for (int mt = 0; mt < 2; mt++) {
        #pragma unroll
        for (int nt = 0; nt < 8; nt++) {
            int n = n0 + wn * 64 + nt * 8 + (lane & 3) * 2;
            int h = n >> 6, e = n & 63;
            #pragma unroll
            for (int half = 0; half < 2; half++) {
                int t = r0 + wm * 32 + mt * 16 + (lane >> 2) + half * 8;
                float v0 = acc[mt][nt][half * 2 + 0];
                float v1 = acc[mt][nt][half * 2 + 1];
                if (z < 2) {
                    int p = e >> 1;
                    float theta = exp2f(-(float)p * (13.287712379549449f / 32.f));
                    float sn, cs;
                    sincosf((float)t * theta, &sn, &cs);
                    float w0 = v0 * cs - v1 * sn;
                    float w1 = v1 * cs + v0 * sn;
                    v0 = w0; v1 = w1;
                }
                if (z == 1) {
                    KTo[((size_t)h * kDH + e) * kT + t]     = __float2half_rn(v0);
                    KTo[((size_t)h * kDH + e + 1) * kT + t] = __float2half_rn(v1);
                } else {
                    __half* O = (z == 0) ? Qo : Vo;
                    *(__half2*)&O[((size_t)h * kT + t) * kDH + e] = __floats2half2_rn(v0, v1);
                }
            }
        }
    }
}

// ---------------- flash attention (fp16 mma): block = (64 q-rows, head), 4 warps ----------------
constexpr int AQP = 36;
constexpr int AKV = 72;

__global__ __launch_bounds__(128) void attn_kernel(
    const __half* __restrict__ Q, const __half* __restrict__ KTr,
    const __half* __restrict__ V, __half* __restrict__ A) {
    __shared__ __align__(16) unsigned QPs[64 * AQP];
    __shared__ __align__(16) unsigned Ks[32 * AKV];
    __shared__ __align__(16) unsigned Vs[32 * AKV];
    int tid = threadIdx.x, lane = tid & 31, w = tid >> 5;
    int h = blockIdx.y;
    int qt = (int)gridDim.x - 1 - (int)blockIdx.x;   // heavy tiles first
    int q0 = qt * 64;
    const __half* Qh  = Q   + ((size_t)h * kT + q0) * kDH;
    const __half* KTh = KTr + (size_t)h * kDH * kT;
    const __half* Vh  = V   + (size_t)h * kT * kDH;

    // stage Q tile (fp16 already pairs-along-dh in memory order)
    #pragma unroll
    for (int it = 0; it < 4; it++) {
        int idx = tid + it * 128;
        int m = idx >> 3, c4 = (idx & 7) * 4;
        *(uint4*)&QPs[m * AQP + c4] = *(const uint4*)&Qh[(size_t)m * kDH + c4 * 2];
    }
    __syncthreads();
    unsigned qf[4][4];
    {
        int m = w * 16 + (lane >> 2);
        #pragma unroll
        for (int kk = 0; kk < 4; kk++) {
            qf[kk][0] = QPs[m * AQP + kk * 8 + (lane & 3)];
            qf[kk][1] = QPs[(m + 8) * AQP + kk * 8 + (lane & 3)];
            qf[kk][2] = QPs[m * AQP + kk * 8 + 4 + (lane & 3)];
            qf[kk][3] = QPs[(m + 8) * AQP + kk * 8 + 4 + (lane & 3)];
        }
    }

    float acc_o[8][4] = {};
    float m0 = -1e30f, m1 = -1e30f, l0 = 0.f, l1 = 0.f;

    for (int kt = 0; kt <= qt; kt++) {
        int k0 = kt * 64;
        __syncthreads();
        // K tile: Ks[dh-pair][key] - interleave rows 2p,2p+1 of KT via byte_perm
        #pragma unroll
        for (int it = 0; it < 4; it++) {
            int idx = tid + it * 128;
            int p = idx >> 4, key4 = (idx & 15) * 4;
            const __half* kp0 = &KTh[(size_t)(2 * p) * kT + k0 + key4];
            uint2 a = *(const uint2*)kp0;
            uint2 bb = *(const uint2*)(kp0 + kT);
            Ks[p * AKV + key4 + 0] = __byte_perm(a.x, bb.x, 0x5410);
            Ks[p * AKV + key4 + 1] = __byte_perm(a.x, bb.x, 0x7632);
            Ks[p * AKV + key4 + 2] = __byte_perm(a.y, bb.y, 0x5410);
            Ks[p * AKV + key4 + 3] = __byte_perm(a.y, bb.y, 0x7632);
        }
        // V tile: Vs[key-pair][dh]
        #pragma unroll
        for (int it = 0; it < 4; it++) {
            int idx = tid + it * 128;
            int kp = idx >> 4, dh4 = (idx & 15) * 4;
            const __half* vp = &Vh[(size_t)(k0 + 2 * kp) * kDH + dh4];
            uint2 a = *(const uint2*)vp;
            uint2 bb = *(const uint2*)(vp + kDH);
            Vs[kp * AKV + dh4 + 0] = __byte_perm(a.x, bb.x, 0x5410);
            Vs[kp * AKV + dh4 + 1] = __byte_perm(a.x, bb.x, 0x7632);
            Vs[kp * AKV + dh4 + 2] = __byte_perm(a.y, bb.y, 0x5410);
            Vs[kp * AKV + dh4 + 3] = __byte_perm(a.y, bb.y, 0x7632);
        }
        __syncthreads();

        // S = Q @ K^T (4 k16 steps over dh=64)
        float s_acc[8][4] = {};
        #pragma unroll
        for (int kk = 0; kk < 4; kk++) {
            #pragma unroll
            for (int nt = 0; nt < 8; nt++) {
                unsigned bf[2];
                bf[0] = Ks[(kk * 8 + (lane & 3)) * AKV + nt * 8 + (lane >> 2)];
                bf[1] = Ks[(kk * 8 + 4 + (lane & 3)) * AKV + nt * 8 + (lane >> 2)];
                mma_f16(s_acc[nt], qf[kk], bf);
            }
        }

        float rm0 = -1e30f, rm1 = -1e30f;
        int gq0 = q0 + w * 16 + (lane >> 2);
        #pragma unroll
        for (int nt = 0; nt < 8; nt++) {
            #pragma unroll
            for (int c = 0; c < 4; c++) {
                float v = s_acc[nt][c] * 0.125f;
                if (kt == qt) {
                    int key = k0 + nt * 8 + 2 * (lane & 3) + (c & 1);
                    int gq = gq0 + (c >> 1) * 8;
                    if (key > gq) v = -1e30f;
                }
                s_acc[nt][c] = v;
                if ((c >> 1) == 0) rm0 = fmaxf(rm0, v); else rm1 = fmaxf(rm1, v);
            }
        }
        #pragma unroll
        for (int o = 1; o <= 2; o <<= 1) {
            rm0 = fmaxf(rm0, __shfl_xor_sync(0xffffffffu, rm0, o));
            rm1 = fmaxf(rm1, __shfl_xor_sync(0xffffffffu, rm1, o));
        }
        float nm0 = fmaxf(m0, rm0), nm1 = fmaxf(m1, rm1);
        float sc0 = __expf(m0 - nm0), sc1 = __expf(m1 - nm1);
        m0 = nm0; m1 = nm1;

        float rs0 = 0.f, rs1 = 0.f;
        int prow = w * 16 + (lane >> 2);
        #pragma unroll
        for (int nt = 0; nt < 8; nt++) {
            float p0 = __expf(s_acc[nt][0] - nm0);
            float p1 = __expf(s_acc[nt][1] - nm0);
            float p2 = __expf(s_acc[nt][2] - nm1);
            float p3 = __expf(s_acc[nt][3] - nm1);
            rs0 += p0 + p1; rs1 += p2 + p3;
            QPs[prow * AQP + nt * 4 + (lane & 3)]       = pk2(p0, p1);
            QPs[(prow + 8) * AQP + nt * 4 + (lane & 3)] = pk2(p2, p3);
        }
        #pragma unroll
        for (int o = 1; o <= 2; o <<= 1) {
            rs0 += __shfl_xor_sync(0xffffffffu, rs0, o);
            rs1 += __shfl_xor_sync(0xffffffffu, rs1, o);
        }
        l0 = l0 * sc0 + rs0;
        l1 = l1 * sc1 + rs1;
        #pragma unroll
        for (int nt = 0; nt < 8; nt++) {
            acc_o[nt][0] *= sc0; acc_o[nt][1] *= sc0;
            acc_o[nt][2] *= sc1; acc_o[nt][3] *= sc1;
        }
        __syncwarp();

        // O += P @ V (4 k16 steps over 64 keys)
        #pragma unroll
        for (int kk = 0; kk < 4; kk++) {
            unsigned pf[4];
            int m = w * 16 + (lane >> 2);
            pf[0] = QPs[m * AQP + kk * 8 + (lane & 3)];
            pf[1] = QPs[(m + 8) * AQP + kk * 8 + (lane & 3)];
            pf[2] = QPs[m * AQP + kk * 8 + 4 + (lane & 3)];
            pf[3] = QPs[(m + 8) * AQP + kk * 8 + 4 + (lane & 3)];
            #pragma unroll
            for (int nt = 0; nt < 8; nt++) {
                unsigned bf[2];
                bf[0] = Vs[(kk * 8 + (lane & 3)) * AKV + nt * 8 + (lane >> 2)];
                bf[1] = Vs[(kk * 8 + 4 + (lane & 3)) * AKV + nt * 8 + (lane >> 2)];
                mma_f16(acc_o[nt], pf, bf);
            }
        }
    }

    float inv0 = 1.f / l0, inv1 = 1.f / l1;
    int gq0 = q0 + w * 16 + (lane >> 2);
    #pragma unroll
    for (int nt = 0; nt < 8; nt++) {
        int col = h * kDH + nt * 8 + 2 * (lane & 3);
        *(__half2*)&A[(size_t)gq0 * kD + col] =
            __floats2half2_rn(acc_o[nt][0] * inv0, acc_o[nt][1] * inv0);
        *(__half2*)&A[(size_t)(gq0 + 8) * kD + col] =
            __floats2half2_rn(acc_o[nt][2] * inv1, acc_o[nt][3] * inv1);
    }
}

// ---------------- proj fp16 GEMM + residual, M128 (A read fp16 direct) ----------------
__global__ __launch_bounds__(256) void proj_kernel(
    const __half* __restrict__ A, const float* __restrict__ W,
    const float* __restrict__ bias, const float* __restrict__ emb,
    float* __restrict__ out) {
    GEMM16_SMEM
    int tid = threadIdx.x, lane = tid & 31, w = tid >> 5;
    int wm = w & 3, wn = w >> 2;
    int r0 = blockIdx.x * 128;
    int n0 = blockIdx.y * 128;

    uint2 pa[4];
    uint4 pb[2];

    #define PROJ_LOAD_REGS(k0_) { \
        _Pragma("unroll") \
        for (int p = 0; p < 4; p++) { \
            int m = (tid >> 3) + p * 32; \
            pa[p] = *(const uint2*)&A[(size_t)(r0 + m) * kD + (k0_) + (tid & 7) * 4]; \
        } \
        _Pragma("unroll") \
        for (int p = 0; p < 2; p++) { \
            int kp = (tid >> 5) + p * 8; \
            const float* b0p = &W[(size_t)((k0_) + 2 * kp) * kD + n0 + (tid & 31) * 4]; \
            float4 r0v = *(const float4*)b0p; \
            float4 r1v = *(const float4*)(b0p + kD); \
            pb[p].x = pk2(r0v.x, r1v.x); pb[p].y = pk2(r0v.y, r1v.y); \
            pb[p].z = pk2(r0v.z, r1v.z); pb[p].w = pk2(r0v.w, r1v.w); \
        } \
    }

    float acc[2][8][4] = {};
    PROJ_LOAD_REGS(0)
    GEMM16_STORE_REGS(0)
    __syncthreads();
    for (int k0 = 0, i = 0; k0 < kD; k0 += 32, i++) {
        if (k0 + 32 < kD) PROJ_LOAD_REGS(k0 + 32)
        GEMM16_COMPUTE(i & 1)
        if (k0 + 32 < kD) GEMM16_STORE_REGS((i + 1) & 1)
        __syncthreads();
    }
    #undef PROJ_LOAD_REGS

    #pragma unroll
    for (int mt = 0; mt < 2; mt++) {
        #pragma unroll
        for (int nt = 0; nt < 8; nt++) {
            int c = n0 + wn * 64 + nt * 8 + (lane & 3) * 2;
            #pragma unroll
            for (int half = 0; half < 2; half++) {
                int r = r0 + wm * 32 + mt * 16 + (lane >> 2) + half * 8;
                float2 e2 = *(const float2*)&emb[(size_t)r * kD + c];
                float2 r2;
                r2.x = e2.x + acc[mt][nt][half * 2 + 0] + bias[c];
                r2.y = e2.y + acc[mt][nt][half * 2 + 1] + bias[c + 1];
                *(float2*)&out[(size_t)r * kD + c] = r2;
            }
        }
    }
}

// ---------------- fused offsets + aux + scatter (single block) ----------------
__global__ void offsets_scatter_kernel(float* __restrict__ out, int out_size) {
    int tid = threadIdx.x;
    if (tid == 0) {
        int off = 0;
        g_poff[0] = 0;
        for (int e = 0; e < kE; e++) {
            int pc = (g_counts[e] + 127) & ~127;
            off += pc;
            g_poff[e + 1] = off;
            g_cursor[e] = g_poff[e];
        }
        float aux = 0.f;
        for (int e = 0; e < kE; e++) {
            float imp = g_impsum[e] / (float)kT;
            float dlt = imp - 1.f / (float)kE;
            aux += dlt * dlt;
        }
        aux *= 1.f / (float)kE;
        if (out_size > kT * kD) out[kT * kD] = aux;
    }
    __syncthreads();
    for (int i = tid; i < kT * 2; i += blockDim.x) {
        int e = g_ids[i];
        int pos = atomicAdd(&g_cursor[e], 1);
        g_slot_token[pos] = i >> 1;
        g_slotpos[i] = pos;
    }
}

// ---------------- F1 fp16 GEMM: h = relu(...) -> fp16 out, M128 (A fp16 direct) ----------------
__global__ __launch_bounds__(256) void f1_kernel(
    const __half* __restrict__ y, const float* __restrict__ W1,
    const float* __restrict__ b1) {
    GEMM16_SMEM
    __shared__ int tok[128];
    __shared__ int sh_total, sh_e;
    int tid = threadIdx.x, lane = tid & 31, w = tid >> 5;
    int wm = w & 3, wn = w >> 2;
    int s0 = blockIdx.x * 128;
    if (tid == 0) {
        sh_total = g_poff[kE];
        int e = 0;
        while (e < kE - 1 && s0 >= g_poff[e + 1]) e++;
        sh_e = e;
    }
    if (tid < 128) tok[tid] = g_slot_token[s0 + tid];
    __syncthreads();
    if (s0 >= sh_total) return;
    int e = sh_e;
    const float* W = W1 + (size_t)e * kD * kDFF;
    int f0 = blockIdx.y * 128;
    int atok[4];
    #pragma unroll
    for (int p = 0; p < 4; p++) atok[p] = tok[(tid >> 3) + p * 32];

    uint2 pa[4];
    uint4 pb[2];

    #define F1_LOAD_REGS(k0_) { \
        _Pragma("unroll") \
        for (int p = 0; p < 4; p++) { \
            int t = atok[p]; \
            if (t >= 0) { \
                pa[p] = *(const uint2*)&y[(size_t)t * kD + (k0_) + (tid & 7) * 4]; \
            } else { pa[p].x = 0u; pa[p].y = 0u; } \
        } \
        _Pragma("unroll") \
        for (int p = 0; p < 2; p++) { \
            int kp = (tid >> 5) + p * 8; \
            const float* b0p = &W[(size_t)((k0_) + 2 * kp) * kDFF + f0 + (tid & 31) * 4]; \
            float4 r0v = *(const float4*)b0p; \
            float4 r1v = *(const float4*)(b0p + kDFF); \
            pb[p].x = pk2(r0v.x, r1v.x); pb[p].y = pk2(r0v.y, r1v.y); \
            pb[p].z = pk2(r0v.z, r1v.z); pb[p].w = pk2(r0v.w, r1v.w); \
        } \
    }

    float acc[2][8][4] = {};
    F1_LOAD_REGS(0)
    GEMM16_STORE_REGS(0)
    __syncthreads();
    for (int k0 = 0, i = 0; k0 < kD; k0 += 32, i++) {
        if (k0 + 32 < kD) F1_LOAD_REGS(k0 + 32)
        GEMM16_COMPUTE(i & 1)
        if (k0 + 32 < kD) GEMM16_STORE_REGS((i + 1) & 1)
        __syncthreads();
    }
    #undef F1_LOAD_REGS

    #pragma unroll
    for (int mt = 0; mt < 2; mt++) {
        #pragma unroll
        for (int nt = 0; nt < 8; nt++) {
            int c = f0 + wn * 64 + nt * 8 + (lane & 3) * 2;
            float bb0 = b1[(size_t)e * kDFF + c];
            float bb1 = b1[(size_t)e * kDFF + c + 1];
            #pragma unroll
            for (int half = 0; half < 2; half++) {
                int r = s0 + wm * 32 + mt * 16 + (lane >> 2) + half * 8;
                float h0 = fmaxf(acc[mt][nt][half * 2 + 0] + bb0, 0.f);
                float h1 = fmaxf(acc[mt][nt][half * 2 + 1] + bb1, 0.f);
                __half2 hv = __floats2half2_rn(h0, h1);
                *(__half2*)&g_h[(size_t)r * kDFF + c] = hv;
            }
        }
    }
}

// ---------------- F2 fp16 GEMM: yo = h @ W2[e] + b2[e], M128 ----------------
__global__ __launch_bounds__(256) void f2_kernel(
    const float* __restrict__ W2, const float* __restrict__ b2) {
    GEMM16_SMEM
    __shared__ int sh_total, sh_e;
    int tid = threadIdx.x, lane = tid & 31, w = tid >> 5;
    int wm = w & 3, wn = w >> 2;
    int s0 = blockIdx.x * 128;
    if (tid == 0) {
        sh_total = g_poff[kE];
        int e = 0;
        while (e < kE - 1 && s0 >= g_poff[e + 1]) e++;
        sh_e = e;
    }
    __syncthreads();
    if (s0 >= sh_total) return;
    int e = sh_e;
    const float* W = W2 + (size_t)e * kDFF * kD;
    int c0 = blockIdx.y * 128;

    uint2 pa[4];
    uint4 pb[2];

    #define F2_LOAD_REGS(k0_) { \
        _Pragma("unroll") \
        for (int p = 0; p < 4; p++) { \
            int m = (tid >> 3) + p * 32; \
            pa[p] = *(const uint2*)&g_h[(size_t)(s0 + m) * kDFF + (k0_) + (tid & 7) * 4]; \
        } \
        _Pragma("unroll") \
        for (int p = 0; p < 2; p++) { \
            int kp = (tid >> 5) + p * 8; \
            const float* b0p = &W[(size_t)((k0_) + 2 * kp) * kD + c0 + (tid & 31) * 4]; \
            float4 r0v = *(const float4*)b0p; \
            float4 r1v = *(const float4*)(b0p + kD); \
            pb[p].x = pk2(r0v.x, r1v.x); pb[p].y = pk2(r0v.y, r1v.y); \
            pb[p].z = pk2(r0v.z, r1v.z); pb[p].w = pk2(r0v.w, r1v.w); \
        } \
    }

    float acc[2][8][4] = {};
    F2_LOAD_REGS(0)
    GEMM16_STORE_REGS(0)
    __syncthreads();
    for (int k0 = 0, i = 0; k0 < kDFF; k0 += 32, i++) {
        if (k0 + 32 < kDFF) F2_LOAD_REGS(k0 + 32)
        GEMM16_COMPUTE(i & 1)
        if (k0 + 32 < kDFF) GEMM16_STORE_REGS((i + 1) & 1)
        __syncthreads();
    }
    #undef F2_LOAD_REGS

    #pragma unroll
    for (int mt = 0; mt < 2; mt++) {
        #pragma unroll
        for (int nt = 0; nt < 8; nt++) {
            int c = c0 + wn * 64 + nt * 8 + (lane & 3) * 2;
            float bb0 = b2[(size_t)e * kD + c];
            float bb1 = b2[(size_t)e * kD + c + 1];
            #pragma unroll
            for (int half = 0; half < 2; half++) {
                int r = s0 + wm * 32 + mt * 16 + (lane >> 2) + half * 8;
                float2 r2;
                r2.x = acc[mt][nt][half * 2 + 0] + bb0;
                r2.y = acc[mt][nt][half * 2 + 1] + bb1;
                *(float2*)&g_yo[(size_t)r * kD + c] = r2;
            }
        }
    }
}

// ---------------- combine ----------------
__global__ void combine_kernel(float* __restrict__ out) {
    int idx4 = blockIdx.x * blockDim.x + threadIdx.x;
    if (idx4 >= kT * kD / 4) return;
    int idx = idx4 * 4;
    int n = idx >> 10;
    int d = idx & (kD - 1);
    int p0 = g_slotpos[n * 2], p1 = g_slotpos[n * 2 + 1];
    float g0 = g_gates[n * 2], g1 = g_gates[n * 2 + 1];
    float4 base = *(const float4*)&g_emb2[idx];
    float4 y0 = *(const float4*)&g_yo[(size_t)p0 * kD + d];
    float4 y1 = *(const float4*)&g_yo[(size_t)p1 * kD + d];
    float4 r;
    r.x = base.x + g0 * y0.x + g1 * y1.x;
    r.y = base.y + g0 * y0.y + g1 * y1.y;
    r.z = base.z + g0 * y0.z + g1 * y1.z;
    r.w = base.w + g0 * y0.w + g1 * y1.w;
    *(float4*)&out[idx] = r;
}

// ---------------- launch ----------------
extern "C" void kernel_launch(void* const* d_in, const int* in_sizes, int n_in,
                              void* d_out, int out_size) {
    const float* emb    = (const float*)d_in[0];
    const float* gamma1 = (const float*)d_in[1];
    const float* beta1  = (const float*)d_in[2];
    const float* WQ     = (const float*)d_in[3];
    const float* WK     = (const float*)d_in[4];
    const float* WV     = (const float*)d_in[5];
    const float* Wproj  = (const float*)d_in[6];
    const float* bproj  = (const float*)d_in[7];
    const float* gamma2 = (const float*)d_in[8];
    const float* beta2  = (const float*)d_in[9];
    const float* Wr     = (const float*)d_in[10];
    const float* br     = (const float*)d_in[11];
    const float* W1     = (const float*)d_in[12];
    const float* b1     = (const float*)d_in[13];
    const float* W2     = (const float*)d_in[14];
    const float* b2     = (const float*)d_in[15];
    float* out = (float*)d_out;

    __half* gx;    cudaGetSymbolAddress((void**)&gx, g_x);
    __half* gq;    cudaGetSymbolAddress((void**)&gq, g_q);
    __half* gkT;   cudaGetSymbolAddress((void**)&gkT, g_kT);
    __half* gv;    cudaGetSymbolAddress((void**)&gv, g_v);
    __half* gattn; cudaGetSymbolAddress((void**)&gattn, g_attn);
    float*  gemb2; cudaGetSymbolAddress((void**)&gemb2, g_emb2);
    __half* gy;    cudaGetSymbolAddress((void**)&gy, g_y);

    ln_kernel<<<kT, 256>>>(emb, gamma1, beta1, gx);
    qkv_kernel<<<dim3(kT / 128, (kH * kDH) / 128, 3), 256>>>(gx, WQ, WK, WV, gq, gkT, gv);
    attn_kernel<<<dim3(kT / 64, kH), 128>>>(gq, gkT, gv, gattn);
    proj_kernel<<<dim3(kT / 128, kD / 128), 256>>>(gattn, Wproj, bproj, emb, gemb2);
    ln2_router_kernel<<<kT, 256>>>(gemb2, gamma2, beta2, gy, Wr, br);
    offsets_scatter_kernel<<<1, 1024>>>(out, out_size);
    f1_kernel<<<dim3(kSlots / 128, kDFF / 128), 256>>>(gy, W1, b1);
    f2_kernel<<<dim3(kSlots / 128, kD / 128), 256>>>(W2, b2);
    combine_kernel<<<(kT * kD / 4 + 255) / 256, 256>>>(out);
}

// round 17
// speedup vs baseline: 1.0589x; 1.0092x over previous
#include <cuda_runtime.h>
#include <cuda_fp16.h>
#include <math.h>

// ---------------- problem constants ----------------
constexpr int kT   = 1024;
constexpr int kD   = 1024;
constexpr int kH   = 16;
constexpr int kDH  = 64;
constexpr int kE   = 8;
constexpr int kDFF = 4096;
constexpr int kSlots = 3072;   // 2048 assignments + per-expert pad to 128

// ---------------- device scratch ----------------
__device__ __half g_x[kT * kD];          // LN1 out
__device__ __half g_q[kH * kT * kDH];
__device__ __half g_kT[kH * kDH * kT];   // K transposed [h][dh][t]
__device__ __half g_v[kH * kT * kDH];
__device__ __half g_attn[kT * kD];
__device__ __half g_y[kT * kD];          // LN2 out
__device__ __half g_h[kSlots * kDFF];    // expert hidden
__device__ float2 g_rope[kT * (kDH / 2)]; // (cos,sin) per (t, pair)
__device__ int   g_ids[kT * 2];
__device__ float g_gates[kT * 2];
__device__ int   g_counts[kE];
__device__ int   g_poff[kE + 1];
__device__ int   g_cursor[kE];
__device__ int   g_slot_token[kSlots];
__device__ float g_slot_gate[kSlots];
__device__ float g_impsum[kE];

// ---------------- mma helpers ----------------
__device__ __forceinline__ void mma_f16(float c[4], const unsigned a[4], const unsigned b[2]) {
    asm volatile("mma.sync.aligned.m16n8k16.row.col.f32.f16.f16.f32 "
        "{%0,%1,%2,%3}, {%4,%5,%6,%7}, {%8,%9}, {%0,%1,%2,%3};\n"
        : "+f"(c[0]), "+f"(c[1]), "+f"(c[2]), "+f"(c[3])
        : "r"(a[0]), "r"(a[1]), "r"(a[2]), "r"(a[3]), "r"(b[0]), "r"(b[1]));
}
__device__ __forceinline__ unsigned pk2(float a, float b) {
    __half2 h = __floats2half2_rn(a, b);
    return *(unsigned*)&h;
}

constexpr int ASTR = 20;
constexpr int BSTR = 136;

// ======== M128 tile (256 thr, warp tile 32x64, double-buffered) ========
#define GEMM16_SMEM \
    __shared__ __align__(16) unsigned As[2][128 * ASTR]; \
    __shared__ __align__(16) unsigned Bs[2][16 * BSTR];

#define GEMM16_COMPUTE(buf) \
    _Pragma("unroll") \
    for (int p0 = 0; p0 < 16; p0 += 8) { \
        unsigned bf[8][2]; \
        _Pragma("unroll") \
        for (int nt = 0; nt < 8; nt++) { \
            int n = wn * 64 + nt * 8 + (lane >> 2); \
            bf[nt][0] = Bs[buf][(p0 + (lane & 3)) * BSTR + n]; \
            bf[nt][1] = Bs[buf][(p0 + 4 + (lane & 3)) * BSTR + n]; \
        } \
        _Pragma("unroll") \
        for (int mt = 0; mt < 2; mt++) { \
            int m = wm * 32 + mt * 16 + (lane >> 2); \
            unsigned af[4]; \
            af[0] = As[buf][m * ASTR + p0 + (lane & 3)]; \
            af[1] = As[buf][(m + 8) * ASTR + p0 + (lane & 3)]; \
            af[2] = As[buf][m * ASTR + p0 + 4 + (lane & 3)]; \
            af[3] = As[buf][(m + 8) * ASTR + p0 + 4 + (lane & 3)]; \
            _Pragma("unroll") \
            for (int nt = 0; nt < 8; nt++) mma_f16(acc[mt][nt], af, bf[nt]); \
        } \
    }

#define GEMM16_STORE_REGS(buf) \
    _Pragma("unroll") \
    for (int p = 0; p < 4; p++) \
        *(uint2*)&As[buf][((tid >> 3) + p * 32) * ASTR + (tid & 7) * 2] = pa[p]; \
    _Pragma("unroll") \
    for (int p = 0; p < 2; p++) \
        *(uint4*)&Bs[buf][((tid >> 5) + p * 8) * BSTR + (tid & 31) * 4] = pb[p];

// ======== M64 tile (256 thr, warp tile 16x64, double-buffered) ========
#define GEMM16_SMEM64 \
    __shared__ __align__(16) unsigned As[2][64 * ASTR]; \
    __shared__ __align__(16) unsigned Bs[2][16 * BSTR];

#define GEMM16_COMPUTE64(buf) \
    _Pragma("unroll") \
    for (int p0 = 0; p0 < 16; p0 += 8) { \
        unsigned bf[8][2]; \
        _Pragma("unroll") \
        for (int nt = 0; nt < 8; nt++) { \
            int n = wn * 64 + nt * 8 + (lane >> 2); \
            bf[nt][0] = Bs[buf][(p0 + (lane & 3)) * BSTR + n]; \
            bf[nt][1] = Bs[buf][(p0 + 4 + (lane & 3)) * BSTR + n]; \
        } \
        { \
            int m = wm * 16 + (lane >> 2); \
            unsigned af[4]; \
            af[0] = As[buf][m * ASTR + p0 + (lane & 3)]; \
            af[1] = As[buf][(m + 8) * ASTR + p0 + (lane & 3)]; \
            af[2] = As[buf][m * ASTR + p0 + 4 + (lane & 3)]; \
            af[3] = As[buf][(m + 8) * ASTR + p0 + 4 + (lane & 3)]; \
            _Pragma("unroll") \
            for (int nt = 0; nt < 8; nt++) mma_f16(acc[nt], af, bf[nt]); \
        } \
    }

#define GEMM16_STORE_REGS64(buf) \
    _Pragma("unroll") \
    for (int p = 0; p < 2; p++) \
        *(uint2*)&As[buf][((tid >> 3) + p * 32) * ASTR + (tid & 7) * 2] = pa[p]; \
    _Pragma("unroll") \
    for (int p = 0; p < 2; p++) \
        *(uint4*)&Bs[buf][((tid >> 5) + p * 8) * BSTR + (tid & 31) * 4] = pb[p];

// ---------------- misc helpers ----------------
__device__ __forceinline__ float block_reduce_sum(float v) {
    __shared__ float sh[32];
    int lane = threadIdx.x & 31, w = threadIdx.x >> 5;
    #pragma unroll
    for (int o = 16; o > 0; o >>= 1) v += __shfl_xor_sync(0xffffffffu, v, o);
    if (lane == 0) sh[w] = v;
    __syncthreads();
    if (w == 0) {
        v = (lane < (int)(blockDim.x >> 5)) ? sh[lane] : 0.f;
        #pragma unroll
        for (int o = 16; o > 0; o >>= 1) v += __shfl_xor_sync(0xffffffffu, v, o);
        if (lane == 0) sh[0] = v;
    }
    __syncthreads();
    float r = sh[0];
    __syncthreads();
    return r;
}

// ---------------- LN1 (+ folded reset + RoPE table init), fp16 out ----------------
__global__ void ln_kernel(const float* __restrict__ in, const float* __restrict__ g,
                          const float* __restrict__ b, __half* __restrict__ out) {
    int gi = blockIdx.x * blockDim.x + threadIdx.x;
    if (gi < kSlots) g_slot_token[gi] = -1;
    if (gi < kE) { g_counts[gi] = 0; g_impsum[gi] = 0.f; }
    if (gi < kT * (kDH / 2)) {
        int t = gi >> 5, p = gi & 31;
        float theta = exp2f(-(float)p * (13.287712379549449f / 32.f));
        float sn, cs;
        sincosf((float)t * theta, &sn, &cs);
        g_rope[gi] = make_float2(cs, sn);
    }

    int row = blockIdx.x;
    const float* x = in + (size_t)row * kD;
    float s = 0.f;
    for (int i = threadIdx.x; i < kD; i += blockDim.x) s += x[i];
    float mean = block_reduce_sum(s) * (1.f / kD);
    float v = 0.f;
    for (int i = threadIdx.x; i < kD; i += blockDim.x) {
        float d = x[i] - mean; v += d * d;
    }
    float var = block_reduce_sum(v) * (1.f / kD);
    float rstd = rsqrtf(var + 1e-6f);
    __half* o = out + (size_t)row * kD;
    for (int i = threadIdx.x * 2; i < kD; i += blockDim.x * 2) {
        float v0 = (x[i] - mean) * rstd * g[i] + b[i];
        float v1 = (x[i + 1] - mean) * rstd * g[i + 1] + b[i + 1];
        *(__half2*)&o[i] = __floats2half2_rn(v0, v1);
    }
}

// ---------------- fused LN2 + router (reads emb2 from out buffer), fp16 y out ----------------
__global__ void ln2_router_kernel(const float* __restrict__ in,
                                  const float* __restrict__ g, const float* __restrict__ b,
                                  __half* __restrict__ out,
                                  const float* __restrict__ Wr, const float* __restrict__ br) {
    int row = blockIdx.x;
    const float* x = in + (size_t)row * kD;
    float s = 0.f;
    for (int i = threadIdx.x; i < kD; i += blockDim.x) s += x[i];
    float mean = block_reduce_sum(s) * (1.f / kD);
    float v = 0.f;
    for (int i = threadIdx.x; i < kD; i += blockDim.x) {
        float d = x[i] - mean; v += d * d;
    }
    float var = block_reduce_sum(v) * (1.f / kD);
    float rstd = rsqrtf(var + 1e-6f);
    __half* o = out + (size_t)row * kD;
    float rs[kE];
    #pragma unroll
    for (int e = 0; e < kE; e++) rs[e] = 0.f;
    for (int i = threadIdx.x * 2; i < kD; i += blockDim.x * 2) {
        float v0 = (x[i] - mean) * rstd * g[i] + b[i];
        float v1 = (x[i + 1] - mean) * rstd * g[i + 1] + b[i + 1];
        *(__half2*)&o[i] = __floats2half2_rn(v0, v1);
        const float* wr0 = Wr + (size_t)i * kE;
        #pragma unroll
        for (int e = 0; e < kE; e++) rs[e] += v0 * wr0[e] + v1 * wr0[kE + e];
    }
    #pragma unroll
    for (int e = 0; e < kE; e++) rs[e] = block_reduce_sum(rs[e]);
    if (threadIdx.x == 0) {
        float w[kE];
        float mx = -1e30f;
        #pragma unroll
        for (int e = 0; e < kE; e++) { w[e] = rs[e] + br[e]; mx = fmaxf(mx, w[e]); }
        float sum = 0.f;
        #pragma unroll
        for (int e = 0; e < kE; e++) { w[e] = __expf(w[e] - mx); sum += w[e]; }
        float inv = 1.f / sum;
        #pragma unroll
        for (int e = 0; e < kE; e++) w[e] *= inv;
        int i0 = 0;
        #pragma unroll
        for (int e = 1; e < kE; e++) if (w[e] > w[i0]) i0 = e;
        int i1 = -1;
        #pragma unroll
        for (int e = 0; e < kE; e++) if (e != i0 && (i1 < 0 || w[e] > w[i1])) i1 = e;
        float norm = w[i0] + w[i1];
        g_ids[row * 2]     = i0;
        g_ids[row * 2 + 1] = i1;
        g_gates[row * 2]     = w[i0] / norm;
        g_gates[row * 2 + 1] = w[i1] / norm;
        atomicAdd(&g_counts[i0], 1);
        atomicAdd(&g_counts[i1], 1);
        #pragma unroll
        for (int e = 0; e < kE; e++) atomicAdd(&g_impsum[e], w[e]);
    }
}

// ---------------- QKV fp16 GEMM + fused RoPE (table), M128 ----------------
__global__ __launch_bounds__(256) void qkv_kernel(
    const __half* __restrict__ x,
    const float* __restrict__ WQ, const float* __restrict__ WK, const float* __restrict__ WV,
    __half* __restrict__ Qo, __half* __restrict__ KTo, __half* __restrict__ Vo) {
    GEMM16_SMEM
    int tid = threadIdx.x, lane = tid & 31, w = tid >> 5;
    int wm = w & 3, wn = w >> 2;
    int r0 = blockIdx.x * 128;
    int n0 = blockIdx.y * 128;
    int z = blockIdx.z;
    const float* W = (z == 0) ? WQ : (z == 1) ? WK : WV;

    int bn4 = (tid & 31) * 4;
    int bh = (n0 + bn4) >> 6, be = (n0 + bn4) & 63;
    uint2 pa[4];
    uint4 pb[2];

    #define QKV_LOAD_REGS(k0_) { \
        _Pragma("unroll") \
        for (int p = 0; p < 4; p++) { \
            int m = (tid >> 3) + p * 32; \
            pa[p] = *(const uint2*)&x[(size_t)(r0 + m) * kD + (k0_) + (tid & 7) * 4]; \
        } \
        _Pragma("unroll") \
        for (int p = 0; p < 2; p++) { \
            int kp = (tid >> 5) + p * 8; \
            const float* b0p = &W[((size_t)bh * kD + (k0_) + 2 * kp) * kDH + be]; \
            float4 r0v = *(const float4*)b0p; \
            float4 r1v = *(const float4*)(b0p + kDH); \
            pb[p].x = pk2(r0v.x, r1v.x); pb[p].y = pk2(r0v.y, r1v.y); \
            pb[p].z = pk2(r0v.z, r1v.z); pb[p].w = pk2(r0v.w, r1v.w); \
        } \
    }

    float acc[2][8][4] = {};
    QKV_LOAD_REGS(0)
    GEMM16_STORE_REGS(0)
    __syncthreads();
    for (int k0 = 0, i = 0; k0 < kD; k0 += 32, i++) {
        if (k0 + 32 < kD) QKV_LOAD_REGS(k0 + 32)
        GEMM16_COMPUTE(i & 1)
        if (k0 + 32 < kD) GEMM16_STORE_REGS((i + 1) & 1)
        __syncthreads();
    }
    #undef QKV_LOAD_REGS

    #pragma unroll
    for (int mt = 0; mt < 2; mt++) {
        #pragma unroll
        for (int nt = 0; nt < 8; nt++) {
            int n = n0 + wn * 64 + nt * 8 + (lane & 3) * 2;
            int h = n >> 6, e = n & 63;
            #pragma unroll
            for (int half = 0; half < 2; half++) {
                int t = r0 + wm * 32 + mt * 16 + (lane >> 2) + half * 8;
                float v0 = acc[mt][nt][half * 2 + 0];
                float v1 = acc[mt][nt][half * 2 + 1];
                if (z < 2) {
                    float2 cs2 = g_rope[t * (kDH / 2) + (e >> 1)];
                    float w0 = v0 * cs2.x - v1 * cs2.y;
                    float w1 = v1 * cs2.x + v0 * cs2.y;
                    v0 = w0; v1 = w1;
                }
                if (z == 1) {
                    KTo[((size_t)h * kDH + e) * kT + t]     = __float2half_rn(v0);
                    KTo[((size_t)h * kDH + e + 1) * kT + t] = __float2half_rn(v1);
                } else {
                    __half* O = (z == 0) ? Qo : Vo;
                    *(__half2*)&O[((size_t)h * kT + t) * kDH + e] = __floats2half2_rn(v0, v1);
                }
            }
        }
    }
}

// ---------------- flash attention (fp16 mma): block = (64 q-rows, head), 4 warps ----------------
constexpr int AQP = 36;
constexpr int AKV = 72;

__global__ __launch_bounds__(128) void attn_kernel(
    const __half* __restrict__ Q, const __half* __restrict__ KTr,
    const __half* __restrict__ V, __half* __restrict__ A) {
    __shared__ __align__(16) unsigned QPs[64 * AQP];
    __shared__ __align__(16) unsigned Ks[32 * AKV];
    __shared__ __align__(16) unsigned Vs[32 * AKV];
    int tid = threadIdx.x, lane = tid & 31, w = tid >> 5;
    int h = blockIdx.y;
    int qt = (int)gridDim.x - 1 - (int)blockIdx.x;   // heavy tiles first
    int q0 = qt * 64;
    const __half* Qh  = Q   + ((size_t)h * kT + q0) * kDH;
    const __half* KTh = KTr + (size_t)h * kDH * kT;
    const __half* Vh  = V   + (size_t)h * kT * kDH;

    #pragma unroll
    for (int it = 0; it < 4; it++) {
        int idx = tid + it * 128;
        int m = idx >> 3, c4 = (idx & 7) * 4;
        *(uint4*)&QPs[m * AQP + c4] = *(const uint4*)&Qh[(size_t)m * kDH + c4 * 2];
    }
    __syncthreads();
    unsigned qf[4][4];
    {
        int m = w * 16 + (lane >> 2);
        #pragma unroll
        for (int kk = 0; kk < 4; kk++) {
            qf[kk][0] = QPs[m * AQP + kk * 8 + (lane & 3)];
            qf[kk][1] = QPs[(m + 8) * AQP + kk * 8 + (lane & 3)];
            qf[kk][2] = QPs[m * AQP + kk * 8 + 4 + (lane & 3)];
            qf[kk][3] = QPs[(m + 8) * AQP + kk * 8 + 4 + (lane & 3)];
        }
    }

    float acc_o[8][4] = {};
    float m0 = -1e30f, m1 = -1e30f, l0 = 0.f, l1 = 0.f;

    for (int kt = 0; kt <= qt; kt++) {
        int k0 = kt * 64;
        __syncthreads();
        #pragma unroll
        for (int it = 0; it < 4; it++) {
            int idx = tid + it * 128;
            int p = idx >> 4, key4 = (idx & 15) * 4;
            const __half* kp0 = &KTh[(size_t)(2 * p) * kT + k0 + key4];
            uint2 a = *(const uint2*)kp0;
            uint2 bb = *(const uint2*)(kp0 + kT);
            Ks[p * AKV + key4 + 0] = __byte_perm(a.x, bb.x, 0x5410);
            Ks[p * AKV + key4 + 1] = __byte_perm(a.x, bb.x, 0x7632);
            Ks[p * AKV + key4 + 2] = __byte_perm(a.y, bb.y, 0x5410);
            Ks[p * AKV + key4 + 3] = __byte_perm(a.y, bb.y, 0x7632);
        }
        #pragma unroll
        for (int it = 0; it < 4; it++) {
            int idx = tid + it * 128;
            int kp = idx >> 4, dh4 = (idx & 15) * 4;
            const __half* vp = &Vh[(size_t)(k0 + 2 * kp) * kDH + dh4];
            uint2 a = *(const uint2*)vp;
            uint2 bb = *(const uint2*)(vp + kDH);
            Vs[kp * AKV + dh4 + 0] = __byte_perm(a.x, bb.x, 0x5410);
            Vs[kp * AKV + dh4 + 1] = __byte_perm(a.x, bb.x, 0x7632);
            Vs[kp * AKV + dh4 + 2] = __byte_perm(a.y, bb.y, 0x5410);
            Vs[kp * AKV + dh4 + 3] = __byte_perm(a.y, bb.y, 0x7632);
        }
        __syncthreads();

        float s_acc[8][4] = {};
        #pragma unroll
        for (int kk = 0; kk < 4; kk++) {
            #pragma unroll
            for (int nt = 0; nt < 8; nt++) {
                unsigned bf[2];
                bf[0] = Ks[(kk * 8 + (lane & 3)) * AKV + nt * 8 + (lane >> 2)];
                bf[1] = Ks[(kk * 8 + 4 + (lane & 3)) * AKV + nt * 8 + (lane >> 2)];
                mma_f16(s_acc[nt], qf[kk], bf);
            }
        }

        float rm0 = -1e30f, rm1 = -1e30f;
        int gq0 = q0 + w * 16 + (lane >> 2);
        #pragma unroll
        for (int nt = 0; nt < 8; nt++) {
            #pragma unroll
            for (int c = 0; c < 4; c++) {
                float v = s_acc[nt][c] * 0.125f;
                if (kt == qt) {
                    int key = k0 + nt * 8 + 2 * (lane & 3) + (c & 1);
                    int gq = gq0 + (c >> 1) * 8;
                    if (key > gq) v = -1e30f;
                }
                s_acc[nt][c] = v;
                if ((c >> 1) == 0) rm0 = fmaxf(rm0, v); else rm1 = fmaxf(rm1, v);
            }
        }
        #pragma unroll
        for (int o = 1; o <= 2; o <<= 1) {
            rm0 = fmaxf(rm0, __shfl_xor_sync(0xffffffffu, rm0, o));
            rm1 = fmaxf(rm1, __shfl_xor_sync(0xffffffffu, rm1, o));
        }
        float nm0 = fmaxf(m0, rm0), nm1 = fmaxf(m1, rm1);
        float sc0 = __expf(m0 - nm0), sc1 = __expf(m1 - nm1);
        m0 = nm0; m1 = nm1;

        float rs0 = 0.f, rs1 = 0.f;
        int prow = w * 16 + (lane >> 2);
        #pragma unroll
        for (int nt = 0; nt < 8; nt++) {
            float p0 = __expf(s_acc[nt][0] - nm0);
            float p1 = __expf(s_acc[nt][1] - nm0);
            float p2 = __expf(s_acc[nt][2] - nm1);
            float p3 = __expf(s_acc[nt][3] - nm1);
            rs0 += p0 + p1; rs1 += p2 + p3;
            QPs[prow * AQP + nt * 4 + (lane & 3)]       = pk2(p0, p1);
            QPs[(prow + 8) * AQP + nt * 4 + (lane & 3)] = pk2(p2, p3);
        }
        #pragma unroll
        for (int o = 1; o <= 2; o <<= 1) {
            rs0 += __shfl_xor_sync(0xffffffffu, rs0, o);
            rs1 += __shfl_xor_sync(0xffffffffu, rs1, o);
        }
        l0 = l0 * sc0 + rs0;
        l1 = l1 * sc1 + rs1;
        #pragma unroll
        for (int nt = 0; nt < 8; nt++) {
            acc_o[nt][0] *= sc0; acc_o[nt][1] *= sc0;
            acc_o[nt][2] *= sc1; acc_o[nt][3] *= sc1;
        }
        __syncwarp();

        #pragma unroll
        for (int kk = 0; kk < 4; kk++) {
            unsigned pf[4];
            int m = w * 16 + (lane >> 2);
            pf[0] = QPs[m * AQP + kk * 8 + (lane & 3)];
            pf[1] = QPs[(m + 8) * AQP + kk * 8 + (lane & 3)];
            pf[2] = QPs[m * AQP + kk * 8 + 4 + (lane & 3)];
            pf[3] = QPs[(m + 8) * AQP + kk * 8 + 4 + (lane & 3)];
            #pragma unroll
            for (int nt = 0; nt < 8; nt++) {
                unsigned bf[2];
                bf[0] = Vs[(kk * 8 + (lane & 3)) * AKV + nt * 8 + (lane >> 2)];
                bf[1] = Vs[(kk * 8 + 4 + (lane & 3)) * AKV + nt * 8 + (lane >> 2)];
                mma_f16(acc_o[nt], pf, bf);
            }
        }
    }

    float inv0 = 1.f / l0, inv1 = 1.f / l1;
    int gq0 = q0 + w * 16 + (lane >> 2);
    #pragma unroll
    for (int nt = 0; nt < 8; nt++) {
        int col = h * kDH + nt * 8 + 2 * (lane & 3);
        *(__half2*)&A[(size_t)gq0 * kD + col] =
            __floats2half2_rn(acc_o[nt][0] * inv0, acc_o[nt][1] * inv0);
        *(__half2*)&A[(size_t)(gq0 + 8) * kD + col] =
            __floats2half2_rn(acc_o[nt][2] * inv1, acc_o[nt][3] * inv1);
    }
}

// ---------------- proj fp16 GEMM + residual -> out (emb2), M64 tile ----------------
__global__ __launch_bounds__(256) void proj_kernel(
    const __half* __restrict__ A, const float* __restrict__ W,
    const float* __restrict__ bias, const float* __restrict__ emb,
    float* __restrict__ out) {
    GEMM16_SMEM64
    int tid = threadIdx.x, lane = tid & 31, w = tid >> 5;
    int wm = w & 3, wn = w >> 2;
    int r0 = blockIdx.x * 64;
    int n0 = blockIdx.y * 128;

    uint2 pa[2];
    uint4 pb[2];

    #define PROJ_LOAD_REGS(k0_) { \
        _Pragma("unroll") \
        for (int p = 0; p < 2; p++) { \
            int m = (tid >> 3) + p * 32; \
            pa[p] = *(const uint2*)&A[(size_t)(r0 + m) * kD + (k0_) + (tid & 7) * 4]; \
        } \
        _Pragma("unroll") \
        for (int p = 0; p < 2; p++) { \
            int kp = (tid >> 5) + p * 8; \
            const float* b0p = &W[(size_t)((k0_) + 2 * kp) * kD + n0 + (tid & 31) * 4]; \
            float4 r0v = *(const float4*)b0p; \
            float4 r1v = *(const float4*)(b0p + kD); \
            pb[p].x = pk2(r0v.x, r1v.x); pb[p].y = pk2(r0v.y, r1v.y); \
            pb[p].z = pk2(r0v.z, r1v.z); pb[p].w = pk2(r0v.w, r1v.w); \
        } \
    }

    float acc[8][4] = {};
    PROJ_LOAD_REGS(0)
    GEMM16_STORE_REGS64(0)
    __syncthreads();
    for (int k0 = 0, i = 0; k0 < kD; k0 += 32, i++) {
        if (k0 + 32 < kD) PROJ_LOAD_REGS(k0 + 32)
        GEMM16_COMPUTE64(i & 1)
        if (k0 + 32 < kD) GEMM16_STORE_REGS64((i + 1) & 1)
        __syncthreads();
    }
    #undef PROJ_LOAD_REGS

    #pragma unroll
    for (int nt = 0; nt < 8; nt++) {
        int c = n0 + wn * 64 + nt * 8 + (lane & 3) * 2;
        #pragma unroll
        for (int half = 0; half < 2; half++) {
            int r = r0 + wm * 16 + (lane >> 2) + half * 8;
            float2 e2 = *(const float2*)&emb[(size_t)r * kD + c];
            float2 r2;
            r2.x = e2.x + acc[nt][half * 2 + 0] + bias[c];
            r2.y = e2.y + acc[nt][half * 2 + 1] + bias[c + 1];
            *(float2*)&out[(size_t)r * kD + c] = r2;
        }
    }
}

// ---------------- fused offsets + aux + scatter (single block) ----------------
__global__ void offsets_scatter_kernel(float* __restrict__ out, int out_size) {
    int tid = threadIdx.x;
    if (tid == 0) {
        int off = 0;
        g_poff[0] = 0;
        for (int e = 0; e < kE; e++) {
            int pc = (g_counts[e] + 127) & ~127;
            off += pc;
            g_poff[e + 1] = off;
            g_cursor[e] = g_poff[e];
        }
        float aux = 0.f;
        for (int e = 0; e < kE; e++) {
            float imp = g_impsum[e] / (float)kT;
            float dlt = imp - 1.f / (float)kE;
            aux += dlt * dlt;
        }
        aux *= 1.f / (float)kE;
        if (out_size > kT * kD) out[kT * kD] = aux;
    }
    __syncthreads();
    for (int i = tid; i < kT * 2; i += blockDim.x) {
        int e = g_ids[i];
        int pos = atomicAdd(&g_cursor[e], 1);
        g_slot_token[pos] = i >> 1;
        g_slot_gate[pos] = g_gates[i];
    }
}

// ---------------- F1 fp16 GEMM: h = relu(...) -> fp16 out, M128 ----------------
__global__ __launch_bounds__(256) void f1_kernel(
    const __half* __restrict__ y, const float* __restrict__ W1,
    const float* __restrict__ b1) {
    GEMM16_SMEM
    __shared__ int tok[128];
    __shared__ int sh_total, sh_e;
    int tid = threadIdx.x, lane = tid & 31, w = tid >> 5;
    int wm = w & 3, wn = w >> 2;
    int s0 = blockIdx.x * 128;
    if (tid == 0) {
        sh_total = g_poff[kE];
        int e = 0;
        while (e < kE - 1 && s0 >= g_poff[e + 1]) e++;
        sh_e = e;
    }
    if (tid < 128) tok[tid] = g_slot_token[s0 + tid];
    __syncthreads();
    if (s0 >= sh_total) return;
    int e = sh_e;
    const float* W = W1 + (size_t)e * kD * kDFF;
    int f0 = blockIdx.y * 128;
    int atok[4];
    #pragma unroll
    for (int p = 0; p < 4; p++) atok[p] = tok[(tid >> 3) + p * 32];

    uint2 pa[4];
    uint4 pb[2];

    #define F1_LOAD_REGS(k0_) { \
        _Pragma("unroll") \
        for (int p = 0; p < 4; p++) { \
            int t = atok[p]; \
            if (t >= 0) { \
                pa[p] = *(const uint2*)&y[(size_t)t * kD + (k0_) + (tid & 7) * 4]; \
            } else { pa[p].x = 0u; pa[p].y = 0u; } \
        } \
        _Pragma("unroll") \
        for (int p = 0; p < 2; p++) { \
            int kp = (tid >> 5) + p * 8; \
            const float* b0p = &W[(size_t)((k0_) + 2 * kp) * kDFF + f0 + (tid & 31) * 4]; \
            float4 r0v = *(const float4*)b0p; \
            float4 r1v = *(const float4*)(b0p + kDFF); \
            pb[p].x = pk2(r0v.x, r1v.x); pb[p].y = pk2(r0v.y, r1v.y); \
            pb[p].z = pk2(r0v.z, r1v.z); pb[p].w = pk2(r0v.w, r1v.w); \
        } \
    }

    float acc[2][8][4] = {};
    F1_LOAD_REGS(0)
    GEMM16_STORE_REGS(0)
    __syncthreads();
    for (int k0 = 0, i = 0; k0 < kD; k0 += 32, i++) {
        if (k0 + 32 < kD) F1_LOAD_REGS(k0 + 32)
        GEMM16_COMPUTE(i & 1)
        if (k0 + 32 < kD) GEMM16_STORE_REGS((i + 1) & 1)
        __syncthreads();
    }
    #undef F1_LOAD_REGS

    #pragma unroll
    for (int mt = 0; mt < 2; mt++) {
        #pragma unroll
        for (int nt = 0; nt < 8; nt++) {
            int c = f0 + wn * 64 + nt * 8 + (lane & 3) * 2;
            float bb0 = b1[(size_t)e * kDFF + c];
            float bb1 = b1[(size_t)e * kDFF + c + 1];
            #pragma unroll
            for (int half = 0; half < 2; half++) {
                int r = s0 + wm * 32 + mt * 16 + (lane >> 2) + half * 8;
                float h0 = fmaxf(acc[mt][nt][half * 2 + 0] + bb0, 0.f);
                float h1 = fmaxf(acc[mt][nt][half * 2 + 1] + bb1, 0.f);
                __half2 hv = __floats2half2_rn(h0, h1);
                *(__half2*)&g_h[(size_t)r * kDFF + c] = hv;
            }
        }
    }
}

// ---------------- F2 fp16 GEMM + fused combine: out += gate * (h @ W2 + b2), M128 ----------------
__global__ __launch_bounds__(256) void f2_kernel(
    const float* __restrict__ W2, const float* __restrict__ b2,
    float* __restrict__ out) {
    GEMM16_SMEM
    __shared__ int tok[128];
    __shared__ float gts[128];
    __shared__ int sh_total, sh_e;
    int tid = threadIdx.x, lane = tid & 31, w = tid >> 5;
    int wm = w & 3, wn = w >> 2;
    int s0 = blockIdx.x * 128;
    if (tid == 0) {
        sh_total = g_poff[kE];
        int e = 0;
        while (e < kE - 1 && s0 >= g_poff[e + 1]) e++;
        sh_e = e;
    }
    if (tid < 128) {
        tok[tid] = g_slot_token[s0 + tid];
        gts[tid] = g_slot_gate[s0 + tid];
    }
    __syncthreads();
    if (s0 >= sh_total) return;
    int e = sh_e;
    const float* W = W2 + (size_t)e * kDFF * kD;
    int c0 = blockIdx.y * 128;

    uint2 pa[4];
    uint4 pb[2];

    #define F2_LOAD_REGS(k0_) { \
        _Pragma("unroll") \
        for (int p = 0; p < 4; p++) { \
            int m = (tid >> 3) + p * 32; \
            pa[p] = *(const uint2*)&g_h[(size_t)(s0 + m) * kDFF + (k0_) + (tid & 7) * 4]; \
        } \
        _Pragma("unroll") \
        for (int p = 0; p < 2; p++) { \
            int kp = (tid >> 5) + p * 8; \
            const float* b0p = &W[(size_t)((k0_) + 2 * kp) * kD + c0 + (tid & 31) * 4]; \
            float4 r0v = *(const float4*)b0p; \
            float4 r1v = *(const float4*)(b0p + kD); \
            pb[p].x = pk2(r0v.x, r1v.x); pb[p].y = pk2(r0v.y, r1v.y); \
            pb[p].z = pk2(r0v.z, r1v.z); pb[p].w = pk2(r0v.w, r1v.w); \
        } \
    }

    float acc[2][8][4] = {};
    F2_LOAD_REGS(0)
    GEMM16_STORE_REGS(0)
    __syncthreads();
    for (int k0 = 0, i = 0; k0 < kDFF; k0 += 32, i++) {
        if (k0 + 32 < kDFF) F2_LOAD_REGS(k0 + 32)
        GEMM16_COMPUTE(i & 1)
        if (k0 + 32 < kDFF) GEMM16_STORE_REGS((i + 1) & 1)
        __syncthreads();
    }
    #undef F2_LOAD_REGS

    #pragma unroll
    for (int mt = 0; mt < 2; mt++) {
        #pragma unroll
        for (int nt = 0; nt < 8; nt++) {
            int c = c0 + wn * 64 + nt * 8 + (lane & 3) * 2;
            float bb0 = b2[(size_t)e * kD + c];
            float bb1 = b2[(size_t)e * kD + c + 1];
            #pragma unroll
            for (int half = 0; half < 2; half++) {
                int lr = wm * 32 + mt * 16 + (lane >> 2) + half * 8;
                int t = tok[lr];
                if (t >= 0) {
                    float gt = gts[lr];
                    atomicAdd(&out[(size_t)t * kD + c],     gt * (acc[mt][nt][half * 2 + 0] + bb0));
                    atomicAdd(&out[(size_t)t * kD + c + 1], gt * (acc[mt][nt][half * 2 + 1] + bb1));
                }
            }
        }
    }
}

// ---------------- launch ----------------
extern "C" void kernel_launch(void* const* d_in, const int* in_sizes, int n_in,
                              void* d_out, int out_size) {
    const float* emb    = (const float*)d_in[0];
    const float* gamma1 = (const float*)d_in[1];
    const float* beta1  = (const float*)d_in[2];
    const float* WQ     = (const float*)d_in[3];
    const float* WK     = (const float*)d_in[4];
    const float* WV     = (const float*)d_in[5];
    const float* Wproj  = (const float*)d_in[6];
    const float* bproj  = (const float*)d_in[7];
    const float* gamma2 = (const float*)d_in[8];
    const float* beta2  = (const float*)d_in[9];
    const float* Wr     = (const float*)d_in[10];
    const float* br     = (const float*)d_in[11];
    const float* W1     = (const float*)d_in[12];
    const float* b1     = (const float*)d_in[13];
    const float* W2     = (const float*)d_in[14];
    const float* b2     = (const float*)d_in[15];
    float* out = (float*)d_out;

    __half* gx;    cudaGetSymbolAddress((void**)&gx, g_x);
    __half* gq;    cudaGetSymbolAddress((void**)&gq, g_q);
    __half* gkT;   cudaGetSymbolAddress((void**)&gkT, g_kT);
    __half* gv;    cudaGetSymbolAddress((void**)&gv, g_v);
    __half* gattn; cudaGetSymbolAddress((void**)&gattn, g_attn);
    __half* gy;    cudaGetSymbolAddress((void**)&gy, g_y);

    ln_kernel<<<kT, 256>>>(emb, gamma1, beta1, gx);
    qkv_kernel<<<dim3(kT / 128, (kH * kDH) / 128, 3), 256>>>(gx, WQ, WK, WV, gq, gkT, gv);
    attn_kernel<<<dim3(kT / 64, kH), 128>>>(gq, gkT, gv, gattn);
    proj_kernel<<<dim3(kT / 64, kD / 128), 256>>>(gattn, Wproj, bproj, emb, out);
    ln2_router_kernel<<<kT, 256>>>(out, gamma2, beta2, gy, Wr, br);
    offsets_scatter_kernel<<<1, 1024>>>(out, out_size);
    f1_kernel<<<dim3(kSlots / 128, kDFF / 128), 256>>>(gy, W1, b1);
    f2_kernel<<<dim3(kSlots / 128, kD / 128), 256>>>(W2, b2, out);
}